// round 1
// baseline (speedup 1.0000x reference)
#include <cuda_runtime.h>
#include <math.h>

#define NHH 12
#define DKK 64
#define DVV 128
#define BB  4
#define LL  2048
#define HH  1024
#define KD  768
#define VD  1536
#define BL  (BB*LL)

// ---------------- scratch (allocation-free: __device__ globals) ----------------
__device__ float g_bufQ [BL*KD];
__device__ float g_bufK [BL*KD];
__device__ float g_bufV [BL*VD];
__device__ float g_bufG [BL*VD];
__device__ float g_bufQc[BL*KD];
__device__ float g_bufKc[BL*KD];
__device__ float g_bufVc[BL*VD];
__device__ float g_bufO [BL*VD];
__device__ float g_gk   [BL*NHH];
__device__ float g_beta [BL*NHH];

// ---------------- tiled fp32 GEMM: C[M,N] = A[M,K] * B[K,N] ----------------
// BM=BN=128, BK=8, 256 threads, 8x8 per-thread microtile.
// Requires M%128==0, N%128==0, K%8==0 (true for all calls here).
__global__ void sgemm128(const float* __restrict__ A, const float* __restrict__ B,
                         float* __restrict__ C, int M, int N, int K) {
    __shared__ float As[8][128];
    __shared__ float Bs[8][128];

    const int tid = threadIdx.x;
    const int bx = blockIdx.x;   // N tile
    const int by = blockIdx.y;   // M tile

    // A tile loads: 128 rows x 8 cols = 256 float4 loads (one per thread)
    const int arow = tid >> 1;
    const int acol = (tid & 1) * 4;
    // B tile loads: 8 rows x 128 cols = 256 float4 loads
    const int brow = tid >> 5;
    const int bcol = (tid & 31) * 4;

    const int tr = tid / 16;     // 0..15 -> M micro
    const int tc = tid % 16;     // 0..15 -> N micro

    const float* Ab = A + (size_t)(by * 128) * K;
    const float* Bb = B + bx * 128;

    float acc[8][8];
#pragma unroll
    for (int i = 0; i < 8; i++)
#pragma unroll
        for (int j = 0; j < 8; j++) acc[i][j] = 0.f;

    for (int k0 = 0; k0 < K; k0 += 8) {
        float4 a = *(const float4*)(Ab + (size_t)arow * K + k0 + acol);
        As[acol + 0][arow] = a.x;
        As[acol + 1][arow] = a.y;
        As[acol + 2][arow] = a.z;
        As[acol + 3][arow] = a.w;
        float4 b = *(const float4*)(Bb + (size_t)(k0 + brow) * N + bcol);
        *(float4*)&Bs[brow][bcol] = b;
        __syncthreads();

#pragma unroll
        for (int kk = 0; kk < 8; kk++) {
            float ar[8], br[8];
#pragma unroll
            for (int i = 0; i < 8; i++) ar[i] = As[kk][tr * 8 + i];
#pragma unroll
            for (int j = 0; j < 8; j++) br[j] = Bs[kk][tc * 8 + j];
#pragma unroll
            for (int i = 0; i < 8; i++)
#pragma unroll
                for (int j = 0; j < 8; j++) acc[i][j] += ar[i] * br[j];
        }
        __syncthreads();
    }

#pragma unroll
    for (int i = 0; i < 8; i++) {
        int row = by * 128 + tr * 8 + i;
        float* Cr = C + (size_t)row * N + bx * 128 + tc * 8;
        float4 v0 = make_float4(acc[i][0], acc[i][1], acc[i][2], acc[i][3]);
        float4 v1 = make_float4(acc[i][4], acc[i][5], acc[i][6], acc[i][7]);
        *(float4*)(Cr + 0) = v0;
        *(float4*)(Cr + 4) = v1;
    }
}

// ---------------- gk / beta projection (N=12 each) ----------------
__global__ void gkbeta_kernel(const float* __restrict__ hs,
                              const float* __restrict__ Wgk, const float* __restrict__ Wb,
                              const float* __restrict__ bb,  const float* __restrict__ A_log,
                              const float* __restrict__ dt_bias,
                              float* __restrict__ gk, float* __restrict__ beta) {
    int row = blockIdx.x;   // 0..BL-1
    __shared__ float xs[HH];
    for (int i = threadIdx.x; i < HH; i += blockDim.x) xs[i] = hs[(size_t)row * HH + i];
    __syncthreads();
    int t = threadIdx.x;
    if (t < NHH) {
        float acc = dt_bias[t];
        for (int k = 0; k < HH; k++) acc += xs[k] * Wgk[k * NHH + t];
        float sp = (acc > 20.f) ? acc : log1pf(expf(acc));
        gk[row * NHH + t] = -expf(A_log[t]) * sp;
    } else if (t < 2 * NHH) {
        int h = t - NHH;
        float acc = bb[h];
        for (int k = 0; k < HH; k++) acc += xs[k] * Wb[k * NHH + h];
        beta[row * NHH + h] = 1.f / (1.f + expf(-acc));
    }
}

// ---------------- causal dwconv(K=4) + silu + per-head l2norm (q, k) ----------------
// grid: BL*NH blocks, 64 threads (one per DK channel)
__global__ void conv_silu_l2(const float* __restrict__ in, const float* __restrict__ w,
                             float* __restrict__ out) {
    int idx = blockIdx.x;
    int h  = idx % NHH;
    int bl = idx / NHH;      // b*L + l
    int l  = bl % LL;
    int c  = h * DKK + threadIdx.x;
    const float* wr = w + c * 4;
    float acc = 0.f;
#pragma unroll
    for (int j = 0; j < 4; j++) {
        int tt = l - 3 + j;
        if (tt >= 0) acc += in[(size_t)(bl - l + tt) * KD + c] * wr[j];
    }
    float sv = acc / (1.f + expf(-acc));   // silu
    float ss = sv * sv;
#pragma unroll
    for (int off = 16; off; off >>= 1) ss += __shfl_xor_sync(0xffffffffu, ss, off);
    __shared__ float sred[2];
    if ((threadIdx.x & 31) == 0) sred[threadIdx.x >> 5] = ss;
    __syncthreads();
    float n = sqrtf(sred[0] + sred[1]);
    out[(size_t)bl * KD + c] = sv / fmaxf(n, 1e-12f);
}

// ---------------- causal dwconv(K=4) + silu (v) ----------------
__global__ void conv_silu_v(const float* __restrict__ in, const float* __restrict__ w,
                            float* __restrict__ out, int total) {
    int gid = blockIdx.x * blockDim.x + threadIdx.x;
    if (gid >= total) return;
    int c  = gid % VD;
    int bl = gid / VD;
    int l  = bl % LL;
    const float* wr = w + c * 4;
    float acc = 0.f;
#pragma unroll
    for (int j = 0; j < 4; j++) {
        int tt = l - 3 + j;
        if (tt >= 0) acc += in[(size_t)(bl - l + tt) * VD + c] * wr[j];
    }
    out[gid] = acc / (1.f + expf(-acc));
}

// ---------------- gated delta rule recurrence ----------------
// 48 blocks (b,h), 128 threads; thread owns one V-column (64 state regs)
__global__ void recur_kernel(const float* __restrict__ q, const float* __restrict__ k,
                             const float* __restrict__ v, const float* __restrict__ gk,
                             const float* __restrict__ beta, float* __restrict__ o) {
    int b = blockIdx.x / NHH, h = blockIdx.x % NHH;
    int tid = threadIdx.x;

    float S[DKK];
#pragma unroll
    for (int i = 0; i < DKK; i++) S[i] = 0.f;

    __shared__ float ksh[DKK], qsh[DKK];
    __shared__ float sg, sb;

    const float* qb = q + (size_t)b * LL * KD + h * DKK;
    const float* kb = k + (size_t)b * LL * KD + h * DKK;
    const float* vb = v + (size_t)b * LL * VD + h * DVV;
    const float* gb = gk + (size_t)b * LL * NHH + h;
    const float* be = beta + (size_t)b * LL * NHH + h;
    float* ob = o + (size_t)b * LL * VD + h * DVV;

    for (int t = 0; t < LL; t++) {
        if (tid < DKK) {
            ksh[tid] = kb[(size_t)t * KD + tid];
            qsh[tid] = qb[(size_t)t * KD + tid];
        }
        if (tid == 64) sg = expf(gb[(size_t)t * NHH]);
        if (tid == 65) sb = be[(size_t)t * NHH];
        float vv = vb[(size_t)t * VD + tid];
        __syncthreads();

        float eg = sg, bt = sb;
        float p0 = 0.f, p1 = 0.f, p2 = 0.f, p3 = 0.f;
#pragma unroll
        for (int i = 0; i < DKK; i += 4) {
            S[i + 0] *= eg; S[i + 1] *= eg; S[i + 2] *= eg; S[i + 3] *= eg;
            p0 += ksh[i + 0] * S[i + 0];
            p1 += ksh[i + 1] * S[i + 1];
            p2 += ksh[i + 2] * S[i + 2];
            p3 += ksh[i + 3] * S[i + 3];
        }
        float delta = bt * (vv - (p0 + p1 + p2 + p3));
        float o0 = 0.f, o1 = 0.f, o2 = 0.f, o3 = 0.f;
#pragma unroll
        for (int i = 0; i < DKK; i += 4) {
            S[i + 0] += ksh[i + 0] * delta; o0 += qsh[i + 0] * S[i + 0];
            S[i + 1] += ksh[i + 1] * delta; o1 += qsh[i + 1] * S[i + 1];
            S[i + 2] += ksh[i + 2] * delta; o2 += qsh[i + 2] * S[i + 2];
            S[i + 3] += ksh[i + 3] * delta; o3 += qsh[i + 3] * S[i + 3];
        }
        ob[(size_t)t * VD + tid] = o0 + o1 + o2 + o3;
        __syncthreads();
    }
}

// ---------------- rmsnorm * gnorm_w * silu(g), in place on o ----------------
// grid: BL*NH blocks, 128 threads
__global__ void rmsgate_kernel(float* __restrict__ o, const float* __restrict__ g,
                               const float* __restrict__ gw) {
    size_t base = (size_t)blockIdx.x * DVV;
    int tid = threadIdx.x;
    float val = o[base + tid];
    float ss = val * val;
#pragma unroll
    for (int off = 16; off; off >>= 1) ss += __shfl_xor_sync(0xffffffffu, ss, off);
    __shared__ float sr[4];
    if ((tid & 31) == 0) sr[tid >> 5] = ss;
    __syncthreads();
    float tot = sr[0] + sr[1] + sr[2] + sr[3];
    float r = rsqrtf(tot / DVV + 1e-5f);
    float gv = g[base + tid];
    float sgt = gv / (1.f + expf(-gv));
    o[base + tid] = val * r * gw[tid] * sgt;
}

// ---------------- launch ----------------
extern "C" void kernel_launch(void* const* d_in, const int* in_sizes, int n_in,
                              void* d_out, int out_size) {
    const float *hs = 0, *Wq = 0, *Wk = 0, *Wv = 0, *Wg = 0, *Wgk = 0, *Wb = 0,
                *bbp = 0, *convq = 0, *convk = 0, *convv = 0, *Alog = 0,
                *dtb = 0, *gnw = 0, *Wo = 0;
    int c786 = 0, c1572 = 0, c12288 = 0, c12 = 0, c3072 = 0;
    for (int i = 0; i < n_in; i++) {
        const float* p = (const float*)d_in[i];
        switch (in_sizes[i]) {
            case 8388608: hs = p; break;
            case 786432:  if (c786++ == 0) Wq = p; else Wk = p; break;
            case 1572864: { int j = c1572++; if (j == 0) Wv = p; else if (j == 1) Wg = p; else Wo = p; } break;
            case 12288:   if (c12288++ == 0) Wgk = p; else Wb = p; break;
            case 12:      { int j = c12++; if (j == 0) bbp = p; else if (j == 1) Alog = p; else dtb = p; } break;
            case 3072:    if (c3072++ == 0) convq = p; else convk = p; break;
            case 6144:    convv = p; break;
            case 128:     gnw = p; break;
            default: break;
        }
    }

    float *bQ, *bK, *bV, *bG, *bQc, *bKc, *bVc, *bO, *bgk, *bbe;
    cudaGetSymbolAddress((void**)&bQ,  g_bufQ);
    cudaGetSymbolAddress((void**)&bK,  g_bufK);
    cudaGetSymbolAddress((void**)&bV,  g_bufV);
    cudaGetSymbolAddress((void**)&bG,  g_bufG);
    cudaGetSymbolAddress((void**)&bQc, g_bufQc);
    cudaGetSymbolAddress((void**)&bKc, g_bufKc);
    cudaGetSymbolAddress((void**)&bVc, g_bufVc);
    cudaGetSymbolAddress((void**)&bO,  g_bufO);
    cudaGetSymbolAddress((void**)&bgk, g_gk);
    cudaGetSymbolAddress((void**)&bbe, g_beta);

    // 1) input projections
    sgemm128<<<dim3(KD / 128, BL / 128), 256>>>(hs, Wq, bQ, BL, KD, HH);
    sgemm128<<<dim3(KD / 128, BL / 128), 256>>>(hs, Wk, bK, BL, KD, HH);
    sgemm128<<<dim3(VD / 128, BL / 128), 256>>>(hs, Wv, bV, BL, VD, HH);
    sgemm128<<<dim3(VD / 128, BL / 128), 256>>>(hs, Wg, bG, BL, VD, HH);

    // 2) gk / beta
    gkbeta_kernel<<<BL, 128>>>(hs, Wgk, Wb, bbp, Alog, dtb, bgk, bbe);

    // 3) conv + silu (+ l2norm for q,k)
    conv_silu_l2<<<BL * NHH, 64>>>(bQ, convq, bQc);
    conv_silu_l2<<<BL * NHH, 64>>>(bK, convk, bKc);
    int totv = BL * VD;
    conv_silu_v<<<(totv + 255) / 256, 256>>>(bV, convv, bVc, totv);

    // 4) recurrence
    recur_kernel<<<BB * NHH, 128>>>(bQc, bKc, bVc, bgk, bbe, bO);

    // 5) rmsnorm + swish gate
    rmsgate_kernel<<<BL * NHH, 128>>>(bO, bG, gnw);

    // 6) output projection
    sgemm128<<<dim3(HH / 128, BL / 128), 256>>>(bO, Wo, (float*)d_out, BL, HH, VD);
}

// round 2
// speedup vs baseline: 1.3798x; 1.3798x over previous
#include <cuda_runtime.h>
#include <math.h>

#define NHH 12
#define DKK 64
#define DVV 128
#define BB  4
#define LL  2048
#define HH  1024
#define KD  768
#define VD  1536
#define BL  (BB*LL)

// ---------------- scratch ----------------
__device__ float g_bufQ [BL*KD];
__device__ float g_bufK [BL*KD];
__device__ float g_bufV [BL*VD];
__device__ float g_bufG [BL*VD];
__device__ float g_bufQc[BL*KD];
__device__ float g_bufKc[BL*KD];
__device__ float g_bufVc[BL*VD];
__device__ float g_bufO [BL*VD];
__device__ float g_gk   [BL*NHH];
__device__ float g_beta [BL*NHH];

// ---------------- double-buffered fp32 GEMM core ----------------
// BM=BN=128, BK=8, 256 threads, 8x8 microtile, ping-pong smem, 1 sync/iter.
struct GemmSmem {
    float As[2][8][128];
    float Bs[2][8][128];
};

__device__ __forceinline__ void gemm_tile(GemmSmem& sm,
                                          const float* __restrict__ A,
                                          const float* __restrict__ B,
                                          float* __restrict__ C,
                                          int N, int K, int by, int bx) {
    const int tid = threadIdx.x;
    const int arow = tid >> 1;
    const int acol = (tid & 1) * 4;
    const int brow = tid >> 5;
    const int bcol = (tid & 31) * 4;
    const int tr = tid / 16;
    const int tc = tid % 16;

    const float* Ab = A + (size_t)(by * 128) * K;
    const float* Bb = B + bx * 128;

    // preload tile 0
    float4 pa = *(const float4*)(Ab + (size_t)arow * K + acol);
    float4 pb = *(const float4*)(Bb + (size_t)brow * N + bcol);
    sm.As[0][acol + 0][arow] = pa.x;
    sm.As[0][acol + 1][arow] = pa.y;
    sm.As[0][acol + 2][arow] = pa.z;
    sm.As[0][acol + 3][arow] = pa.w;
    *(float4*)&sm.Bs[0][brow][bcol] = pb;
    __syncthreads();

    float acc[8][8];
#pragma unroll
    for (int i = 0; i < 8; i++)
#pragma unroll
        for (int j = 0; j < 8; j++) acc[i][j] = 0.f;

    const int nIter = K / 8;
    for (int it = 0; it < nIter; it++) {
        const int cur = it & 1;
        const bool has_next = (it + 1) < nIter;
        float4 na, nb;
        if (has_next) {
            int k0 = (it + 1) * 8;
            na = *(const float4*)(Ab + (size_t)arow * K + k0 + acol);
            nb = *(const float4*)(Bb + (size_t)(k0 + brow) * N + bcol);
        }
#pragma unroll
        for (int kk = 0; kk < 8; kk++) {
            float ar[8], br[8];
#pragma unroll
            for (int i = 0; i < 8; i++) ar[i] = sm.As[cur][kk][tr * 8 + i];
#pragma unroll
            for (int j = 0; j < 8; j++) br[j] = sm.Bs[cur][kk][tc * 8 + j];
#pragma unroll
            for (int i = 0; i < 8; i++)
#pragma unroll
                for (int j = 0; j < 8; j++) acc[i][j] += ar[i] * br[j];
        }
        if (has_next) {
            const int nxt = cur ^ 1;
            sm.As[nxt][acol + 0][arow] = na.x;
            sm.As[nxt][acol + 1][arow] = na.y;
            sm.As[nxt][acol + 2][arow] = na.z;
            sm.As[nxt][acol + 3][arow] = na.w;
            *(float4*)&sm.Bs[nxt][brow][bcol] = nb;
        }
        __syncthreads();
    }

#pragma unroll
    for (int i = 0; i < 8; i++) {
        int row = by * 128 + tr * 8 + i;
        float* Cr = C + (size_t)row * N + bx * 128 + tc * 8;
        *(float4*)(Cr + 0) = make_float4(acc[i][0], acc[i][1], acc[i][2], acc[i][3]);
        *(float4*)(Cr + 4) = make_float4(acc[i][4], acc[i][5], acc[i][6], acc[i][7]);
    }
}

// fused Q/K/V/G projections: 36 N-tiles x 64 M-tiles
__global__ void qkvg_gemm(const float* __restrict__ hs,
                          const float* __restrict__ Wq, const float* __restrict__ Wk,
                          const float* __restrict__ Wv, const float* __restrict__ Wg,
                          float* __restrict__ bQ, float* __restrict__ bK,
                          float* __restrict__ bV, float* __restrict__ bG) {
    __shared__ GemmSmem sm;
    int bx = blockIdx.x, by = blockIdx.y;
    const float* B;
    float* C;
    int N, col;
    if (bx < 6)       { B = Wq; C = bQ; N = KD; col = bx; }
    else if (bx < 12) { B = Wk; C = bK; N = KD; col = bx - 6; }
    else if (bx < 24) { B = Wv; C = bV; N = VD; col = bx - 12; }
    else              { B = Wg; C = bG; N = VD; col = bx - 24; }
    gemm_tile(sm, hs, B, C, N, HH, by, col);
}

__global__ void sgemm_db(const float* __restrict__ A, const float* __restrict__ B,
                         float* __restrict__ C, int N, int K) {
    __shared__ GemmSmem sm;
    gemm_tile(sm, A, B, C, N, K, blockIdx.y, blockIdx.x);
}

// ---------------- gk / beta projection v2 ----------------
// 256 threads = 8 warps, one row per warp; lane j owns output j (coalesced W).
__global__ void gkbeta2(const float* __restrict__ hs,
                        const float* __restrict__ Wgk, const float* __restrict__ Wb,
                        const float* __restrict__ bb,  const float* __restrict__ A_log,
                        const float* __restrict__ dt_bias,
                        float* __restrict__ gk, float* __restrict__ beta) {
    __shared__ float sh[8][HH];
    int w = threadIdx.x >> 5, lane = threadIdx.x & 31;
    int row = blockIdx.x * 8 + w;
    const float* hr = hs + (size_t)row * HH;
    for (int i = lane; i < HH; i += 32) sh[w][i] = hr[i];
    __syncwarp();
    if (lane < 24) {
        const float* W = (lane < 12) ? Wgk : Wb;
        int j = (lane < 12) ? lane : lane - 12;
        float acc = 0.f;
#pragma unroll 4
        for (int k = 0; k < HH; k++) acc += sh[w][k] * W[k * NHH + j];
        if (lane < 12) {
            acc += dt_bias[j];
            float sp = (acc > 20.f) ? acc : log1pf(expf(acc));
            gk[row * NHH + j] = -expf(A_log[j]) * sp;
        } else {
            acc += bb[j];
            beta[row * NHH + j] = 1.f / (1.f + expf(-acc));
        }
    }
}

// ---------------- causal dwconv(K=4) + silu + l2norm (q,k) ----------------
__global__ void conv_silu_l2(const float* __restrict__ in, const float* __restrict__ w,
                             float* __restrict__ out) {
    int idx = blockIdx.x;
    int h  = idx % NHH;
    int bl = idx / NHH;
    int l  = bl % LL;
    int c  = h * DKK + threadIdx.x;
    const float* wr = w + c * 4;
    float acc = 0.f;
#pragma unroll
    for (int j = 0; j < 4; j++) {
        int tt = l - 3 + j;
        if (tt >= 0) acc += in[(size_t)(bl - l + tt) * KD + c] * wr[j];
    }
    float sv = acc / (1.f + expf(-acc));
    float ss = sv * sv;
#pragma unroll
    for (int off = 16; off; off >>= 1) ss += __shfl_xor_sync(0xffffffffu, ss, off);
    __shared__ float sred[2];
    if ((threadIdx.x & 31) == 0) sred[threadIdx.x >> 5] = ss;
    __syncthreads();
    float n = sqrtf(sred[0] + sred[1]);
    out[(size_t)bl * KD + c] = sv / fmaxf(n, 1e-12f);
}

__global__ void conv_silu_v(const float* __restrict__ in, const float* __restrict__ w,
                            float* __restrict__ out, int total) {
    int gid = blockIdx.x * blockDim.x + threadIdx.x;
    if (gid >= total) return;
    int c  = gid % VD;
    int bl = gid / VD;
    int l  = bl % LL;
    const float* wr = w + c * 4;
    float acc = 0.f;
#pragma unroll
    for (int j = 0; j < 4; j++) {
        int tt = l - 3 + j;
        if (tt >= 0) acc += in[(size_t)(bl - l + tt) * VD + c] * wr[j];
    }
    out[gid] = acc / (1.f + expf(-acc));
}

// ---------------- gated delta rule recurrence v2 ----------------
// grid = B*NH*2 (DV split in halves of 64), 128 threads.
// Thread pair (2 per V-column) splits DK: 32 state regs each, shfl_xor(1) reduce.
// Double-buffered k/q smem (1 barrier/step), prefetch of next-step inputs,
// exp(gk)/beta staged in smem once.
__global__ void recur2(const float* __restrict__ q, const float* __restrict__ k,
                       const float* __restrict__ v, const float* __restrict__ gk,
                       const float* __restrict__ beta, float* __restrict__ o) {
    int blk = blockIdx.x;
    int b  = blk / (NHH * 2);
    int h  = (blk >> 1) % NHH;
    int vh = blk & 1;
    int tid = threadIdx.x;
    int col  = tid >> 1;     // 0..63 local V column
    int half = tid & 1;      // DK half

    __shared__ float ksh[2][DKK];
    __shared__ float qsh[2][DKK];
    __shared__ float egsh[LL];
    __shared__ float bsh[LL];

    const float* qb = q + (size_t)b * LL * KD + h * DKK;
    const float* kb = k + (size_t)b * LL * KD + h * DKK;
    const float* vb = v + (size_t)b * LL * VD + h * DVV + vh * 64;
    const float* gb = gk + (size_t)b * LL * NHH + h;
    const float* be = beta + (size_t)b * LL * NHH + h;
    float* ob = o + (size_t)b * LL * VD + h * DVV + vh * 64;

    for (int i = tid; i < LL; i += 128) {
        egsh[i] = expf(gb[(size_t)i * NHH]);
        bsh[i]  = be[(size_t)i * NHH];
    }

    float S[32];
#pragma unroll
    for (int i = 0; i < 32; i++) S[i] = 0.f;

    // prefetch step 0
    float pk = (tid < DKK) ? kb[tid] : qb[tid - DKK];
    float pv = vb[col];
    __syncthreads();   // egsh/bsh ready

    for (int t = 0; t < LL; t++) {
        const int buf = t & 1;
        if (tid < DKK) ksh[buf][tid] = pk;
        else           qsh[buf][tid - DKK] = pk;
        float vv = pv;
        __syncthreads();

        // prefetch t+1 (latency hidden behind compute)
        if (t + 1 < LL) {
            pk = (tid < DKK) ? kb[(size_t)(t + 1) * KD + tid]
                             : qb[(size_t)(t + 1) * KD + tid - DKK];
            pv = vb[(size_t)(t + 1) * VD + col];
        }

        float eg = egsh[t], bt = bsh[t];
        const float* kh = &ksh[buf][half * 32];
        const float* qh = &qsh[buf][half * 32];
        float pred = 0.f;
#pragma unroll
        for (int j = 0; j < 32; j++) {
            S[j] *= eg;
            pred += kh[j] * S[j];
        }
        pred += __shfl_xor_sync(0xffffffffu, pred, 1);
        float delta = bt * (vv - pred);
        float out = 0.f;
#pragma unroll
        for (int j = 0; j < 32; j++) {
            S[j] += kh[j] * delta;
            out += qh[j] * S[j];
        }
        out += __shfl_xor_sync(0xffffffffu, out, 1);
        if (half == 0) ob[(size_t)t * VD + col] = out;
    }
}

// ---------------- rmsnorm * gnorm_w * silu(g) ----------------
__global__ void rmsgate_kernel(float* __restrict__ o, const float* __restrict__ g,
                               const float* __restrict__ gw) {
    size_t base = (size_t)blockIdx.x * DVV;
    int tid = threadIdx.x;
    float val = o[base + tid];
    float ss = val * val;
#pragma unroll
    for (int off = 16; off; off >>= 1) ss += __shfl_xor_sync(0xffffffffu, ss, off);
    __shared__ float sr[4];
    if ((tid & 31) == 0) sr[tid >> 5] = ss;
    __syncthreads();
    float tot = sr[0] + sr[1] + sr[2] + sr[3];
    float r = rsqrtf(tot / DVV + 1e-5f);
    float gv = g[base + tid];
    float sgt = gv / (1.f + expf(-gv));
    o[base + tid] = val * r * gw[tid] * sgt;
}

// ---------------- launch ----------------
extern "C" void kernel_launch(void* const* d_in, const int* in_sizes, int n_in,
                              void* d_out, int out_size) {
    const float *hs = 0, *Wq = 0, *Wk = 0, *Wv = 0, *Wg = 0, *Wgk = 0, *Wb = 0,
                *bbp = 0, *convq = 0, *convk = 0, *convv = 0, *Alog = 0,
                *dtb = 0, *gnw = 0, *Wo = 0;
    int c786 = 0, c1572 = 0, c12288 = 0, c12 = 0, c3072 = 0;
    for (int i = 0; i < n_in; i++) {
        const float* p = (const float*)d_in[i];
        switch (in_sizes[i]) {
            case 8388608: hs = p; break;
            case 786432:  if (c786++ == 0) Wq = p; else Wk = p; break;
            case 1572864: { int j = c1572++; if (j == 0) Wv = p; else if (j == 1) Wg = p; else Wo = p; } break;
            case 12288:   if (c12288++ == 0) Wgk = p; else Wb = p; break;
            case 12:      { int j = c12++; if (j == 0) bbp = p; else if (j == 1) Alog = p; else dtb = p; } break;
            case 3072:    if (c3072++ == 0) convq = p; else convk = p; break;
            case 6144:    convv = p; break;
            case 128:     gnw = p; break;
            default: break;
        }
    }

    float *bQ, *bK, *bV, *bG, *bQc, *bKc, *bVc, *bO, *bgk, *bbe;
    cudaGetSymbolAddress((void**)&bQ,  g_bufQ);
    cudaGetSymbolAddress((void**)&bK,  g_bufK);
    cudaGetSymbolAddress((void**)&bV,  g_bufV);
    cudaGetSymbolAddress((void**)&bG,  g_bufG);
    cudaGetSymbolAddress((void**)&bQc, g_bufQc);
    cudaGetSymbolAddress((void**)&bKc, g_bufKc);
    cudaGetSymbolAddress((void**)&bVc, g_bufVc);
    cudaGetSymbolAddress((void**)&bO,  g_bufO);
    cudaGetSymbolAddress((void**)&bgk, g_gk);
    cudaGetSymbolAddress((void**)&bbe, g_beta);

    // 1) fused input projections
    qkvg_gemm<<<dim3(36, BL / 128), 256>>>(hs, Wq, Wk, Wv, Wg, bQ, bK, bV, bG);

    // 2) gk / beta
    gkbeta2<<<BL / 8, 256>>>(hs, Wgk, Wb, bbp, Alog, dtb, bgk, bbe);

    // 3) conv + silu (+ l2norm for q,k)
    conv_silu_l2<<<BL * NHH, 64>>>(bQ, convq, bQc);
    conv_silu_l2<<<BL * NHH, 64>>>(bK, convk, bKc);
    int totv = BL * VD;
    conv_silu_v<<<(totv + 255) / 256, 256>>>(bV, convv, bVc, totv);

    // 4) recurrence
    recur2<<<BB * NHH * 2, 128>>>(bQc, bKc, bVc, bgk, bbe, bO);

    // 5) rmsnorm + swish gate
    rmsgate_kernel<<<BL * NHH, 128>>>(bO, bG, gnw);

    // 6) output projection
    sgemm_db<<<dim3(HH / 128, BL / 128), 256>>>(bO, Wo, (float*)d_out, HH, VD);
}

// round 3
// speedup vs baseline: 1.3993x; 1.0141x over previous
#include <cuda_runtime.h>
#include <math.h>

#define NHH 12
#define DKK 64
#define DVV 128
#define BB  4
#define LL  2048
#define HH  1024
#define KD  768
#define VD  1536
#define BL  (BB*LL)

typedef unsigned long long u64;

#define FMA2(c, a, b) asm("fma.rn.f32x2 %0, %1, %2, %0;" : "+l"(c) : "l"(a), "l"(b))
#define MUL2(d, a, b) asm("mul.rn.f32x2 %0, %1, %2;" : "=l"(d) : "l"(a), "l"(b))
#define DUP2(d, s)    asm("mov.b64 %0, {%1, %1};" : "=l"(d) : "r"(s))
#define UNPK2(lo, hi, v) asm("mov.b64 {%0, %1}, %2;" : "=r"(lo), "=r"(hi) : "l"(v))

// ---------------- scratch ----------------
__device__ float g_bufQ [BL*KD];
__device__ float g_bufK [BL*KD];
__device__ float g_bufV [BL*VD];
__device__ float g_bufG [BL*VD];
__device__ float g_bufQc[BL*KD];
__device__ float g_bufKc[BL*KD];
__device__ float g_bufVc[BL*VD];
__device__ float g_bufO [BL*VD];
__device__ float g_gk   [BL*NHH];
__device__ float g_beta [BL*NHH];

// ---------------- double-buffered fp32 GEMM core (f32x2 inner loop) ----------------
struct GemmSmem {
    float As[2][8][128];
    float Bs[2][8][128];
};

__device__ __forceinline__ void gemm_tile(GemmSmem& sm,
                                          const float* __restrict__ A,
                                          const float* __restrict__ B,
                                          float* __restrict__ C,
                                          int N, int K, int by, int bx) {
    const int tid = threadIdx.x;
    const int arow = tid >> 1;
    const int acol = (tid & 1) * 4;
    const int brow = tid >> 5;
    const int bcol = (tid & 31) * 4;
    const int tr = tid / 16;
    const int tc = tid % 16;

    const float* Ab = A + (size_t)(by * 128) * K;
    const float* Bb = B + bx * 128;

    float4 pa = *(const float4*)(Ab + (size_t)arow * K + acol);
    float4 pb = *(const float4*)(Bb + (size_t)brow * N + bcol);
    sm.As[0][acol + 0][arow] = pa.x;
    sm.As[0][acol + 1][arow] = pa.y;
    sm.As[0][acol + 2][arow] = pa.z;
    sm.As[0][acol + 3][arow] = pa.w;
    *(float4*)&sm.Bs[0][brow][bcol] = pb;
    __syncthreads();

    u64 acc2[8][4];
#pragma unroll
    for (int i = 0; i < 8; i++)
#pragma unroll
        for (int j = 0; j < 4; j++) acc2[i][j] = 0ull;

    const int nIter = K / 8;
    for (int it = 0; it < nIter; it++) {
        const int cur = it & 1;
        const bool has_next = (it + 1) < nIter;
        float4 na, nb;
        if (has_next) {
            int k0 = (it + 1) * 8;
            na = *(const float4*)(Ab + (size_t)arow * K + k0 + acol);
            nb = *(const float4*)(Bb + (size_t)(k0 + brow) * N + bcol);
        }
#pragma unroll
        for (int kk = 0; kk < 8; kk++) {
            u64 ad[8];
#pragma unroll
            for (int i = 0; i < 8; i++) {
                unsigned int ab = __float_as_uint(sm.As[cur][kk][tr * 8 + i]);
                DUP2(ad[i], ab);
            }
            u64 bd[4];
#pragma unroll
            for (int j = 0; j < 4; j++)
                bd[j] = *(const u64*)&sm.Bs[cur][kk][tc * 8 + j * 2];
#pragma unroll
            for (int i = 0; i < 8; i++)
#pragma unroll
                for (int j = 0; j < 4; j++)
                    FMA2(acc2[i][j], ad[i], bd[j]);
        }
        if (has_next) {
            const int nxt = cur ^ 1;
            sm.As[nxt][acol + 0][arow] = na.x;
            sm.As[nxt][acol + 1][arow] = na.y;
            sm.As[nxt][acol + 2][arow] = na.z;
            sm.As[nxt][acol + 3][arow] = na.w;
            *(float4*)&sm.Bs[nxt][brow][bcol] = nb;
        }
        __syncthreads();
    }

#pragma unroll
    for (int i = 0; i < 8; i++) {
        int row = by * 128 + tr * 8 + i;
        u64* Cr = (u64*)(C + (size_t)row * N + bx * 128 + tc * 8);
        Cr[0] = acc2[i][0];
        Cr[1] = acc2[i][1];
        Cr[2] = acc2[i][2];
        Cr[3] = acc2[i][3];
    }
}

__global__ void qkvg_gemm(const float* __restrict__ hs,
                          const float* __restrict__ Wq, const float* __restrict__ Wk,
                          const float* __restrict__ Wv, const float* __restrict__ Wg,
                          float* __restrict__ bQ, float* __restrict__ bK,
                          float* __restrict__ bV, float* __restrict__ bG) {
    __shared__ GemmSmem sm;
    int bx = blockIdx.x, by = blockIdx.y;
    const float* B;
    float* C;
    int N, col;
    if (bx < 6)       { B = Wq; C = bQ; N = KD; col = bx; }
    else if (bx < 12) { B = Wk; C = bK; N = KD; col = bx - 6; }
    else if (bx < 24) { B = Wv; C = bV; N = VD; col = bx - 12; }
    else              { B = Wg; C = bG; N = VD; col = bx - 24; }
    gemm_tile(sm, hs, B, C, N, HH, by, col);
}

__global__ void sgemm_db(const float* __restrict__ A, const float* __restrict__ B,
                         float* __restrict__ C, int N, int K) {
    __shared__ GemmSmem sm;
    gemm_tile(sm, A, B, C, N, K, blockIdx.y, blockIdx.x);
}

// ---------------- gk / beta projection ----------------
__global__ void gkbeta2(const float* __restrict__ hs,
                        const float* __restrict__ Wgk, const float* __restrict__ Wb,
                        const float* __restrict__ bb,  const float* __restrict__ A_log,
                        const float* __restrict__ dt_bias,
                        float* __restrict__ gk, float* __restrict__ beta) {
    __shared__ float sh[8][HH];
    int w = threadIdx.x >> 5, lane = threadIdx.x & 31;
    int row = blockIdx.x * 8 + w;
    const float* hr = hs + (size_t)row * HH;
    for (int i = lane; i < HH; i += 32) sh[w][i] = hr[i];
    __syncwarp();
    if (lane < 24) {
        const float* W = (lane < 12) ? Wgk : Wb;
        int j = (lane < 12) ? lane : lane - 12;
        float acc = 0.f;
#pragma unroll 4
        for (int k = 0; k < HH; k++) acc += sh[w][k] * W[k * NHH + j];
        if (lane < 12) {
            acc += dt_bias[j];
            float sp = (acc > 20.f) ? acc : log1pf(expf(acc));
            gk[row * NHH + j] = -expf(A_log[j]) * sp;
        } else {
            acc += bb[j];
            beta[row * NHH + j] = 1.f / (1.f + expf(-acc));
        }
    }
}

// ---------------- causal dwconv(K=4) + silu + l2norm (q,k) ----------------
__global__ void conv_silu_l2(const float* __restrict__ in, const float* __restrict__ w,
                             float* __restrict__ out) {
    int idx = blockIdx.x;
    int h  = idx % NHH;
    int bl = idx / NHH;
    int l  = bl % LL;
    int c  = h * DKK + threadIdx.x;
    const float* wr = w + c * 4;
    float acc = 0.f;
#pragma unroll
    for (int j = 0; j < 4; j++) {
        int tt = l - 3 + j;
        if (tt >= 0) acc += in[(size_t)(bl - l + tt) * KD + c] * wr[j];
    }
    float sv = acc / (1.f + expf(-acc));
    float ss = sv * sv;
#pragma unroll
    for (int off = 16; off; off >>= 1) ss += __shfl_xor_sync(0xffffffffu, ss, off);
    __shared__ float sred[2];
    if ((threadIdx.x & 31) == 0) sred[threadIdx.x >> 5] = ss;
    __syncthreads();
    float n = sqrtf(sred[0] + sred[1]);
    out[(size_t)bl * KD + c] = sv / fmaxf(n, 1e-12f);
}

__global__ void conv_silu_v(const float* __restrict__ in, const float* __restrict__ w,
                            float* __restrict__ out, int total) {
    int gid = blockIdx.x * blockDim.x + threadIdx.x;
    if (gid >= total) return;
    int c  = gid % VD;
    int bl = gid / VD;
    int l  = bl % LL;
    const float* wr = w + c * 4;
    float acc = 0.f;
#pragma unroll
    for (int j = 0; j < 4; j++) {
        int tt = l - 3 + j;
        if (tt >= 0) acc += in[(size_t)(bl - l + tt) * VD + c] * wr[j];
    }
    out[gid] = acc / (1.f + expf(-acc));
}

// ---------------- gated delta rule recurrence (f32x2) ----------------
__global__ void recur2(const float* __restrict__ q, const float* __restrict__ k,
                       const float* __restrict__ v, const float* __restrict__ gk,
                       const float* __restrict__ beta, float* __restrict__ o) {
    int blk = blockIdx.x;
    int b  = blk / (NHH * 2);
    int h  = (blk >> 1) % NHH;
    int vh = blk & 1;
    int tid = threadIdx.x;
    int col  = tid >> 1;
    int half = tid & 1;

    __shared__ float ksh[2][DKK];
    __shared__ float qsh[2][DKK];
    __shared__ float egsh[LL];
    __shared__ float bsh[LL];

    const float* qb = q + (size_t)b * LL * KD + h * DKK;
    const float* kb = k + (size_t)b * LL * KD + h * DKK;
    const float* vb = v + (size_t)b * LL * VD + h * DVV + vh * 64;
    const float* gb = gk + (size_t)b * LL * NHH + h;
    const float* be = beta + (size_t)b * LL * NHH + h;
    float* ob = o + (size_t)b * LL * VD + h * DVV + vh * 64;

    for (int i = tid; i < LL; i += 128) {
        egsh[i] = expf(gb[(size_t)i * NHH]);
        bsh[i]  = be[(size_t)i * NHH];
    }

    u64 S2[16];
#pragma unroll
    for (int i = 0; i < 16; i++) S2[i] = 0ull;

    float pk = (tid < DKK) ? kb[tid] : qb[tid - DKK];
    float pv = vb[col];
    __syncthreads();

    for (int t = 0; t < LL; t++) {
        const int buf = t & 1;
        if (tid < DKK) ksh[buf][tid] = pk;
        else           qsh[buf][tid - DKK] = pk;
        float vv = pv;
        __syncthreads();

        if (t + 1 < LL) {
            pk = (tid < DKK) ? kb[(size_t)(t + 1) * KD + tid]
                             : qb[(size_t)(t + 1) * KD + tid - DKK];
            pv = vb[(size_t)(t + 1) * VD + col];
        }

        float eg = egsh[t], bt = bsh[t];
        const u64* kh2 = (const u64*)&ksh[buf][half * 32];
        const u64* qh2 = (const u64*)&qsh[buf][half * 32];

        u64 eg2; DUP2(eg2, __float_as_uint(eg));
        u64 pred2 = 0ull;
#pragma unroll
        for (int j = 0; j < 16; j++) {
            MUL2(S2[j], S2[j], eg2);
            FMA2(pred2, kh2[j], S2[j]);
        }
        unsigned int plo, phi;
        UNPK2(plo, phi, pred2);
        float pred = __uint_as_float(plo) + __uint_as_float(phi);
        pred += __shfl_xor_sync(0xffffffffu, pred, 1);
        float delta = bt * (vv - pred);

        u64 d2; DUP2(d2, __float_as_uint(delta));
        u64 out2 = 0ull;
#pragma unroll
        for (int j = 0; j < 16; j++) {
            FMA2(S2[j], kh2[j], d2);
            FMA2(out2, qh2[j], S2[j]);
        }
        unsigned int olo, ohi;
        UNPK2(olo, ohi, out2);
        float out = __uint_as_float(olo) + __uint_as_float(ohi);
        out += __shfl_xor_sync(0xffffffffu, out, 1);
        if (half == 0) ob[(size_t)t * VD + col] = out;
    }
}

// ---------------- rmsnorm * gnorm_w * silu(g) ----------------
__global__ void rmsgate_kernel(float* __restrict__ o, const float* __restrict__ g,
                               const float* __restrict__ gw) {
    size_t base = (size_t)blockIdx.x * DVV;
    int tid = threadIdx.x;
    float val = o[base + tid];
    float ss = val * val;
#pragma unroll
    for (int off = 16; off; off >>= 1) ss += __shfl_xor_sync(0xffffffffu, ss, off);
    __shared__ float sr[4];
    if ((tid & 31) == 0) sr[tid >> 5] = ss;
    __syncthreads();
    float tot = sr[0] + sr[1] + sr[2] + sr[3];
    float r = rsqrtf(tot / DVV + 1e-5f);
    float gv = g[base + tid];
    float sgt = gv / (1.f + expf(-gv));
    o[base + tid] = val * r * gw[tid] * sgt;
}

// ---------------- launch ----------------
extern "C" void kernel_launch(void* const* d_in, const int* in_sizes, int n_in,
                              void* d_out, int out_size) {
    const float *hs = 0, *Wq = 0, *Wk = 0, *Wv = 0, *Wg = 0, *Wgk = 0, *Wb = 0,
                *bbp = 0, *convq = 0, *convk = 0, *convv = 0, *Alog = 0,
                *dtb = 0, *gnw = 0, *Wo = 0;
    int c786 = 0, c1572 = 0, c12288 = 0, c12 = 0, c3072 = 0;
    for (int i = 0; i < n_in; i++) {
        const float* p = (const float*)d_in[i];
        switch (in_sizes[i]) {
            case 8388608: hs = p; break;
            case 786432:  if (c786++ == 0) Wq = p; else Wk = p; break;
            case 1572864: { int j = c1572++; if (j == 0) Wv = p; else if (j == 1) Wg = p; else Wo = p; } break;
            case 12288:   if (c12288++ == 0) Wgk = p; else Wb = p; break;
            case 12:      { int j = c12++; if (j == 0) bbp = p; else if (j == 1) Alog = p; else dtb = p; } break;
            case 3072:    if (c3072++ == 0) convq = p; else convk = p; break;
            case 6144:    convv = p; break;
            case 128:     gnw = p; break;
            default: break;
        }
    }

    float *bQ, *bK, *bV, *bG, *bQc, *bKc, *bVc, *bO, *bgk, *bbe;
    cudaGetSymbolAddress((void**)&bQ,  g_bufQ);
    cudaGetSymbolAddress((void**)&bK,  g_bufK);
    cudaGetSymbolAddress((void**)&bV,  g_bufV);
    cudaGetSymbolAddress((void**)&bG,  g_bufG);
    cudaGetSymbolAddress((void**)&bQc, g_bufQc);
    cudaGetSymbolAddress((void**)&bKc, g_bufKc);
    cudaGetSymbolAddress((void**)&bVc, g_bufVc);
    cudaGetSymbolAddress((void**)&bO,  g_bufO);
    cudaGetSymbolAddress((void**)&bgk, g_gk);
    cudaGetSymbolAddress((void**)&bbe, g_beta);

    qkvg_gemm<<<dim3(36, BL / 128), 256>>>(hs, Wq, Wk, Wv, Wg, bQ, bK, bV, bG);
    gkbeta2<<<BL / 8, 256>>>(hs, Wgk, Wb, bbp, Alog, dtb, bgk, bbe);
    conv_silu_l2<<<BL * NHH, 64>>>(bQ, convq, bQc);
    conv_silu_l2<<<BL * NHH, 64>>>(bK, convk, bKc);
    int totv = BL * VD;
    conv_silu_v<<<(totv + 255) / 256, 256>>>(bV, convv, bVc, totv);
    recur2<<<BB * NHH * 2, 128>>>(bQc, bKc, bVc, bgk, bbe, bO);
    rmsgate_kernel<<<BL * NHH, 128>>>(bO, bG, gnw);
    sgemm_db<<<dim3(HH / 128, BL / 128), 256>>>(bO, Wo, (float*)d_out, HH, VD);
}

// round 5
// speedup vs baseline: 1.9235x; 1.3746x over previous
#include <cuda_runtime.h>
#include <cuda_bf16.h>
#include <math.h>
#include <cstdint>

#define NHH 12
#define DKK 64
#define DVV 128
#define BB  4
#define LL  2048
#define HH  1024
#define KD  768
#define VD  1536
#define BL  (BB*LL)
#define NTOT 4608   // Q(768)+K(768)+V(1536)+G(1536)

typedef unsigned long long u64;
typedef unsigned int u32;

#define FMA2(c, a, b) asm("fma.rn.f32x2 %0, %1, %2, %0;" : "+l"(c) : "l"(a), "l"(b))
#define MUL2(d, a, b) asm("mul.rn.f32x2 %0, %1, %2;" : "=l"(d) : "l"(a), "l"(b))
#define DUP2(d, s)    asm("mov.b64 %0, {%1, %1};" : "=l"(d) : "r"(s))
#define UNPK2(lo, hi, v) asm("mov.b64 {%0, %1}, %2;" : "=r"(lo), "=r"(hi) : "l"(v))

__device__ __forceinline__ uint32_t smem_to_u32(const void* p) {
    uint32_t a;
    asm("{ .reg .u64 t; cvta.to.shared.u64 t, %1; cvt.u32.u64 %0, t; }" : "=r"(a) : "l"(p));
    return a;
}

#define LDSM4(r0, r1, r2, r3, addr) \
    asm volatile("ldmatrix.sync.aligned.m8n8.x4.shared.b16 {%0,%1,%2,%3}, [%4];" \
        : "=r"(r0), "=r"(r1), "=r"(r2), "=r"(r3) : "r"(addr))

#define MMA16816(c, a, b0, b1) \
    asm volatile("mma.sync.aligned.m16n8k16.row.col.f32.bf16.bf16.f32 " \
        "{%0,%1,%2,%3},{%4,%5,%6,%7},{%8,%9},{%0,%1,%2,%3};" \
        : "+f"((c)[0]), "+f"((c)[1]), "+f"((c)[2]), "+f"((c)[3]) \
        : "r"((a)[0]), "r"((a)[1]), "r"((a)[2]), "r"((a)[3]), "r"(b0), "r"(b1))

__device__ __forceinline__ void cpa16(uint32_t saddr, const void* g) {
    asm volatile("cp.async.cg.shared.global [%0], [%1], 16;" :: "r"(saddr), "l"(g));
}
#define CP_COMMIT() asm volatile("cp.async.commit_group;" ::: "memory")
#define CP_WAIT1()  asm volatile("cp.async.wait_group 1;" ::: "memory")
#define CP_WAIT0()  asm volatile("cp.async.wait_group 0;" ::: "memory")

// ================= scratch =================
__device__ float g_qkvg[(size_t)BL * NTOT];
__device__ __nv_bfloat16 g_hsh[(size_t)BL * HH], g_hsl[(size_t)BL * HH];
__device__ __nv_bfloat16 g_wth[(size_t)NTOT * HH], g_wtl[(size_t)NTOT * HH];
__device__ __nv_bfloat16 g_woth[(size_t)HH * VD], g_wotl[(size_t)HH * VD];
__device__ __nv_bfloat16 g_oh[(size_t)BL * VD], g_ol[(size_t)BL * VD];
__device__ float g_bufQc[BL*KD], g_bufKc[BL*KD], g_bufVc[BL*VD], g_bufO[BL*VD];
__device__ float g_gk[BL*NHH], g_beta[BL*NHH];

// ================= hi/lo split =================
__global__ void split_kernel(const float* __restrict__ in,
                             __nv_bfloat16* __restrict__ oh, __nv_bfloat16* __restrict__ ol, int n) {
    int i = blockIdx.x * 256 + threadIdx.x;
    if (i >= n) return;
    float x = in[i];
    __nv_bfloat16 h = __float2bfloat16(x);
    oh[i] = h;
    ol[i] = __float2bfloat16(x - __bfloat162float(h));
}

// transpose + split: W[K,N] fp32 -> Th/Tl[N,K] bf16
__global__ void transp_split(const float* __restrict__ W, int K, int N,
                             __nv_bfloat16* __restrict__ Th, __nv_bfloat16* __restrict__ Tl) {
    __shared__ float tile[32][33];
    int n0 = blockIdx.x * 32, k0 = blockIdx.y * 32;
    for (int i = threadIdx.y; i < 32; i += 8)
        tile[i][threadIdx.x] = W[(size_t)(k0 + i) * N + n0 + threadIdx.x];
    __syncthreads();
    for (int i = threadIdx.y; i < 32; i += 8) {
        float x = tile[threadIdx.x][i];
        __nv_bfloat16 h = __float2bfloat16(x);
        size_t o = (size_t)(n0 + i) * K + k0 + threadIdx.x;
        Th[o] = h;
        Tl[o] = __float2bfloat16(x - __bfloat162float(h));
    }
}

// ================= mma.sync split-bf16 GEMM =================
// C[M,N](ldc) = sum_k A[m,k]*B[n,k];  A=Ahi+Alo [M,Kdim], B=Bhi+Blo [N,Kdim]
// 128x128 tile, BK=32, 256 thr (8 warps 2x4, warp tile 64x32), cp.async double buffer.
// smem per matrix tile: 128 rows x 40 bf16 (pad) = 10240 B; A:4, B:4 -> 81920 B.
#define TILE_B 10240
#define SMEM_GEMM (8 * TILE_B)

__global__ void __launch_bounds__(256)
gemm_mma(const __nv_bfloat16* __restrict__ Ahi, const __nv_bfloat16* __restrict__ Alo,
         const __nv_bfloat16* __restrict__ Bhi, const __nv_bfloat16* __restrict__ Blo,
         float* __restrict__ C, int Kdim, int ldc) {
    extern __shared__ char smem[];
    const uint32_t smb = smem_to_u32(smem);
    const int tid = threadIdx.x;
    const int lane = tid & 31, w = tid >> 5;
    const int wm = (w & 1) * 64, wn = (w >> 1) * 32;
    const int m0 = blockIdx.y * 128, n0 = blockIdx.x * 128;

    const int rL = tid >> 1;            // load row 0..127
    const int qL = (tid & 1) * 2;       // chunk pair (16B chunks)

    float c[4][4][4];
#pragma unroll
    for (int i = 0; i < 4; i++)
#pragma unroll
        for (int j = 0; j < 4; j++)
#pragma unroll
            for (int e = 0; e < 4; e++) c[i][j][e] = 0.f;

    const int nCh = Kdim >> 5;

    auto load_stage = [&](int kc, int st) {
        const __nv_bfloat16* a0 = Ahi + (size_t)(m0 + rL) * Kdim + kc * 32 + qL * 8;
        const __nv_bfloat16* a1 = Alo + (size_t)(m0 + rL) * Kdim + kc * 32 + qL * 8;
        const __nv_bfloat16* b0 = Bhi + (size_t)(n0 + rL) * Kdim + kc * 32 + qL * 8;
        const __nv_bfloat16* b1 = Blo + (size_t)(n0 + rL) * Kdim + kc * 32 + qL * 8;
        uint32_t sa0 = smb + (st * 2 + 0) * TILE_B + rL * 80 + qL * 16;
        uint32_t sa1 = smb + (st * 2 + 1) * TILE_B + rL * 80 + qL * 16;
        uint32_t sb0 = smb + 4 * TILE_B + (st * 2 + 0) * TILE_B + rL * 80 + qL * 16;
        uint32_t sb1 = smb + 4 * TILE_B + (st * 2 + 1) * TILE_B + rL * 80 + qL * 16;
        cpa16(sa0, a0); cpa16(sa0 + 16, a0 + 8);
        cpa16(sa1, a1); cpa16(sa1 + 16, a1 + 8);
        cpa16(sb0, b0); cpa16(sb0 + 16, b0 + 8);
        cpa16(sb1, b1); cpa16(sb1 + 16, b1 + 8);
        CP_COMMIT();
    };

    load_stage(0, 0);

    for (int kc = 0; kc < nCh; kc++) {
        const int st = kc & 1;
        const bool has_next = (kc + 1) < nCh;
        if (has_next) load_stage(kc + 1, st ^ 1);
        if (has_next) CP_WAIT1(); else CP_WAIT0();
        __syncthreads();

        const int lrow = lane & 15;
        const int lcolB = ((lane >> 4) << 3) * 2;   // 0 or 16 bytes
#pragma unroll
        for (int ks = 0; ks < 2; ks++) {
            const int kbB = ks * 32 + lcolB;        // byte offset of k within row
            uint32_t ah[4][4], al[4][4];
#pragma unroll
            for (int mt = 0; mt < 4; mt++) {
                int row = wm + mt * 16 + lrow;
                uint32_t ad = smb + st * 2 * TILE_B + row * 80 + kbB;
                LDSM4(ah[mt][0], ah[mt][1], ah[mt][2], ah[mt][3], ad);
                LDSM4(al[mt][0], al[mt][1], al[mt][2], al[mt][3], ad + TILE_B);
            }
            uint32_t bh[2][4], bl[2][4];
#pragma unroll
            for (int np = 0; np < 2; np++) {
                int row = wn + np * 16 + lrow;
                uint32_t bd = smb + 4 * TILE_B + st * 2 * TILE_B + row * 80 + kbB;
                LDSM4(bh[np][0], bh[np][1], bh[np][2], bh[np][3], bd);
                LDSM4(bl[np][0], bl[np][1], bl[np][2], bl[np][3], bd + TILE_B);
            }
#pragma unroll
            for (int mt = 0; mt < 4; mt++)
#pragma unroll
                for (int nt = 0; nt < 4; nt++) {
                    int np = nt >> 1, s = nt & 1;
                    MMA16816(c[mt][nt], ah[mt], bh[np][s], bh[np][s + 2]);
                    MMA16816(c[mt][nt], ah[mt], bl[np][s], bl[np][s + 2]);
                    MMA16816(c[mt][nt], al[mt], bh[np][s], bh[np][s + 2]);
                }
        }
        __syncthreads();
    }

    // epilogue
#pragma unroll
    for (int mt = 0; mt < 4; mt++) {
        int row = m0 + wm + mt * 16 + (lane >> 2);
#pragma unroll
        for (int nt = 0; nt < 4; nt++) {
            int col = n0 + wn + nt * 8 + (lane & 3) * 2;
            *(float2*)(C + (size_t)row * ldc + col)       = make_float2(c[mt][nt][0], c[mt][nt][1]);
            *(float2*)(C + (size_t)(row + 8) * ldc + col) = make_float2(c[mt][nt][2], c[mt][nt][3]);
        }
    }
}

// ================= gk / beta projection =================
__global__ void gkbeta2(const float* __restrict__ hs,
                        const float* __restrict__ Wgk, const float* __restrict__ Wb,
                        const float* __restrict__ bb,  const float* __restrict__ A_log,
                        const float* __restrict__ dt_bias,
                        float* __restrict__ gk, float* __restrict__ beta) {
    __shared__ float sh[8][HH];
    int w = threadIdx.x >> 5, lane = threadIdx.x & 31;
    int row = blockIdx.x * 8 + w;
    const float* hr = hs + (size_t)row * HH;
    for (int i = lane; i < HH; i += 32) sh[w][i] = hr[i];
    __syncwarp();
    if (lane < 24) {
        const float* W = (lane < 12) ? Wgk : Wb;
        int j = (lane < 12) ? lane : lane - 12;
        float acc = 0.f;
#pragma unroll 4
        for (int k = 0; k < HH; k++) acc += sh[w][k] * W[k * NHH + j];
        if (lane < 12) {
            acc += dt_bias[j];
            float sp = (acc > 20.f) ? acc : log1pf(expf(acc));
            gk[row * NHH + j] = -expf(A_log[j]) * sp;
        } else {
            acc += bb[j];
            beta[row * NHH + j] = 1.f / (1.f + expf(-acc));
        }
    }
}

// ================= conv + silu (+ l2norm) =================
__global__ void conv_silu_l2(const float* __restrict__ in, int istride,
                             const float* __restrict__ w, float* __restrict__ out) {
    int idx = blockIdx.x;
    int h  = idx % NHH;
    int bl = idx / NHH;
    int l  = bl % LL;
    int c  = h * DKK + threadIdx.x;
    const float* wr = w + c * 4;
    float acc = 0.f;
#pragma unroll
    for (int j = 0; j < 4; j++) {
        int tt = l - 3 + j;
        if (tt >= 0) acc += in[(size_t)(bl - l + tt) * istride + c] * wr[j];
    }
    float sv = acc / (1.f + expf(-acc));
    float ss = sv * sv;
#pragma unroll
    for (int off = 16; off; off >>= 1) ss += __shfl_xor_sync(0xffffffffu, ss, off);
    __shared__ float sred[2];
    if ((threadIdx.x & 31) == 0) sred[threadIdx.x >> 5] = ss;
    __syncthreads();
    float n = sqrtf(sred[0] + sred[1]);
    out[(size_t)bl * KD + c] = sv / fmaxf(n, 1e-12f);
}

__global__ void conv_silu_v(const float* __restrict__ in, int istride,
                            const float* __restrict__ w, float* __restrict__ out, int total) {
    int gid = blockIdx.x * blockDim.x + threadIdx.x;
    if (gid >= total) return;
    int c  = gid % VD;
    int bl = gid / VD;
    int l  = bl % LL;
    const float* wr = w + c * 4;
    float acc = 0.f;
#pragma unroll
    for (int j = 0; j < 4; j++) {
        int tt = l - 3 + j;
        if (tt >= 0) acc += in[(size_t)(bl - l + tt) * istride + c] * wr[j];
    }
    out[gid] = acc / (1.f + expf(-acc));
}

// ================= recurrence (f32x2) =================
__global__ void recur2(const float* __restrict__ q, const float* __restrict__ k,
                       const float* __restrict__ v, const float* __restrict__ gk,
                       const float* __restrict__ beta, float* __restrict__ o) {
    int blk = blockIdx.x;
    int b  = blk / (NHH * 2);
    int h  = (blk >> 1) % NHH;
    int vh = blk & 1;
    int tid = threadIdx.x;
    int col  = tid >> 1;
    int half = tid & 1;

    __shared__ float ksh[2][DKK];
    __shared__ float qsh[2][DKK];
    __shared__ float egsh[LL];
    __shared__ float bsh[LL];

    const float* qb = q + (size_t)b * LL * KD + h * DKK;
    const float* kb = k + (size_t)b * LL * KD + h * DKK;
    const float* vb = v + (size_t)b * LL * VD + h * DVV + vh * 64;
    const float* gb = gk + (size_t)b * LL * NHH + h;
    const float* be = beta + (size_t)b * LL * NHH + h;
    float* ob = o + (size_t)b * LL * VD + h * DVV + vh * 64;

    for (int i = tid; i < LL; i += 128) {
        egsh[i] = expf(gb[(size_t)i * NHH]);
        bsh[i]  = be[(size_t)i * NHH];
    }

    u64 S2[16];
#pragma unroll
    for (int i = 0; i < 16; i++) S2[i] = 0ull;

    float pk = (tid < DKK) ? kb[tid] : qb[tid - DKK];
    float pv = vb[col];
    __syncthreads();

    for (int t = 0; t < LL; t++) {
        const int buf = t & 1;
        if (tid < DKK) ksh[buf][tid] = pk;
        else           qsh[buf][tid - DKK] = pk;
        float vv = pv;
        __syncthreads();

        if (t + 1 < LL) {
            pk = (tid < DKK) ? kb[(size_t)(t + 1) * KD + tid]
                             : qb[(size_t)(t + 1) * KD + tid - DKK];
            pv = vb[(size_t)(t + 1) * VD + col];
        }

        float eg = egsh[t], bt = bsh[t];
        const u64* kh2 = (const u64*)&ksh[buf][half * 32];
        const u64* qh2 = (const u64*)&qsh[buf][half * 32];

        u64 eg2; DUP2(eg2, __float_as_uint(eg));
        u64 pred2 = 0ull;
#pragma unroll
        for (int j = 0; j < 16; j++) {
            MUL2(S2[j], S2[j], eg2);
            FMA2(pred2, kh2[j], S2[j]);
        }
        u32 plo, phi;
        UNPK2(plo, phi, pred2);
        float pred = __uint_as_float(plo) + __uint_as_float(phi);
        pred += __shfl_xor_sync(0xffffffffu, pred, 1);
        float delta = bt * (vv - pred);

        u64 d2; DUP2(d2, __float_as_uint(delta));
        u64 out2 = 0ull;
#pragma unroll
        for (int j = 0; j < 16; j++) {
            FMA2(S2[j], kh2[j], d2);
            FMA2(out2, qh2[j], S2[j]);
        }
        u32 olo, ohi;
        UNPK2(olo, ohi, out2);
        float out = __uint_as_float(olo) + __uint_as_float(ohi);
        out += __shfl_xor_sync(0xffffffffu, out, 1);
        if (half == 0) ob[(size_t)t * VD + col] = out;
    }
}

// ================= rmsnorm * gnorm_w * silu(g) -> hi/lo bf16 =================
__global__ void rmsgate_kernel(const float* __restrict__ o, const float* __restrict__ g,
                               const float* __restrict__ gw,
                               __nv_bfloat16* __restrict__ oh, __nv_bfloat16* __restrict__ ol) {
    int bl = blockIdx.x / NHH, h = blockIdx.x % NHH;
    size_t obase = (size_t)blockIdx.x * DVV;
    size_t gbase = (size_t)bl * NTOT + h * DVV;
    int tid = threadIdx.x;
    float val = o[obase + tid];
    float ss = val * val;
#pragma unroll
    for (int off = 16; off; off >>= 1) ss += __shfl_xor_sync(0xffffffffu, ss, off);
    __shared__ float sr[4];
    if ((tid & 31) == 0) sr[tid >> 5] = ss;
    __syncthreads();
    float tot = sr[0] + sr[1] + sr[2] + sr[3];
    float r = rsqrtf(tot / DVV + 1e-5f);
    float gv = g[gbase + tid];
    float sgt = gv / (1.f + expf(-gv));
    float res = val * r * gw[tid] * sgt;
    __nv_bfloat16 hi = __float2bfloat16(res);
    oh[obase + tid] = hi;
    ol[obase + tid] = __float2bfloat16(res - __bfloat162float(hi));
}

// ================= launch =================
extern "C" void kernel_launch(void* const* d_in, const int* in_sizes, int n_in,
                              void* d_out, int out_size) {
    const float *hs = 0, *Wq = 0, *Wk = 0, *Wv = 0, *Wg = 0, *Wgk = 0, *Wb = 0,
                *bbp = 0, *convq = 0, *convk = 0, *convv = 0, *Alog = 0,
                *dtb = 0, *gnw = 0, *Wo = 0;
    int c786 = 0, c1572 = 0, c12288 = 0, c12 = 0, c3072 = 0;
    for (int i = 0; i < n_in; i++) {
        const float* p = (const float*)d_in[i];
        switch (in_sizes[i]) {
            case 8388608: hs = p; break;
            case 786432:  if (c786++ == 0) Wq = p; else Wk = p; break;
            case 1572864: { int j = c1572++; if (j == 0) Wv = p; else if (j == 1) Wg = p; else Wo = p; } break;
            case 12288:   if (c12288++ == 0) Wgk = p; else Wb = p; break;
            case 12:      { int j = c12++; if (j == 0) bbp = p; else if (j == 1) Alog = p; else dtb = p; } break;
            case 3072:    if (c3072++ == 0) convq = p; else convk = p; break;
            case 6144:    convv = p; break;
            case 128:     gnw = p; break;
            default: break;
        }
    }

    float *qkvg, *bQc, *bKc, *bVc, *bO, *bgk, *bbe;
    __nv_bfloat16 *hsh, *hsl, *wth, *wtl, *woth, *wotl, *oh, *ol;
    cudaGetSymbolAddress((void**)&qkvg, g_qkvg);
    cudaGetSymbolAddress((void**)&hsh,  g_hsh);
    cudaGetSymbolAddress((void**)&hsl,  g_hsl);
    cudaGetSymbolAddress((void**)&wth,  g_wth);
    cudaGetSymbolAddress((void**)&wtl,  g_wtl);
    cudaGetSymbolAddress((void**)&woth, g_woth);
    cudaGetSymbolAddress((void**)&wotl, g_wotl);
    cudaGetSymbolAddress((void**)&oh,   g_oh);
    cudaGetSymbolAddress((void**)&ol,   g_ol);
    cudaGetSymbolAddress((void**)&bQc,  g_bufQc);
    cudaGetSymbolAddress((void**)&bKc,  g_bufKc);
    cudaGetSymbolAddress((void**)&bVc,  g_bufVc);
    cudaGetSymbolAddress((void**)&bO,   g_bufO);
    cudaGetSymbolAddress((void**)&bgk,  g_gk);
    cudaGetSymbolAddress((void**)&bbe,  g_beta);

    cudaFuncSetAttribute(gemm_mma, cudaFuncAttributeMaxDynamicSharedMemorySize, SMEM_GEMM);

    // 1) hi/lo splits + weight transposes
    split_kernel<<<(BL * HH + 255) / 256, 256>>>(hs, hsh, hsl, BL * HH);
    transp_split<<<dim3(KD / 32, HH / 32), dim3(32, 8)>>>(Wq, HH, KD, wth, wtl);
    transp_split<<<dim3(KD / 32, HH / 32), dim3(32, 8)>>>(Wk, HH, KD, wth + (size_t)768 * HH, wtl + (size_t)768 * HH);
    transp_split<<<dim3(VD / 32, HH / 32), dim3(32, 8)>>>(Wv, HH, VD, wth + (size_t)1536 * HH, wtl + (size_t)1536 * HH);
    transp_split<<<dim3(VD / 32, HH / 32), dim3(32, 8)>>>(Wg, HH, VD, wth + (size_t)3072 * HH, wtl + (size_t)3072 * HH);

    // 2) fused QKVG projection on tensor cores
    gemm_mma<<<dim3(NTOT / 128, BL / 128), 256, SMEM_GEMM>>>(hsh, hsl, wth, wtl, qkvg, HH, NTOT);

    // 3) Wo transpose
    transp_split<<<dim3(HH / 32, VD / 32), dim3(32, 8)>>>(Wo, VD, HH, woth, wotl);

    // 4) gk / beta
    gkbeta2<<<BL / 8, 256>>>(hs, Wgk, Wb, bbp, Alog, dtb, bgk, bbe);

    // 5) conv + silu (+ l2norm for q,k)
    conv_silu_l2<<<BL * NHH, 64>>>(qkvg, NTOT, convq, bQc);
    conv_silu_l2<<<BL * NHH, 64>>>(qkvg + 768, NTOT, convk, bKc);
    int totv = BL * VD;
    conv_silu_v<<<(totv + 255) / 256, 256>>>(qkvg + 1536, NTOT, convv, bVc, totv);

    // 6) recurrence
    recur2<<<BB * NHH * 2, 128>>>(bQc, bKc, bVc, bgk, bbe, bO);

    // 7) rmsnorm + swish gate -> hi/lo bf16
    rmsgate_kernel<<<BL * NHH, 128>>>(bO, qkvg + 3072, gnw, oh, ol);

    // 8) output projection on tensor cores
    gemm_mma<<<dim3(HH / 128, BL / 128), 256, SMEM_GEMM>>>(oh, ol, woth, wotl, (float*)d_out, VD, HH);
}

// round 6
// speedup vs baseline: 2.0128x; 1.0464x over previous
#include <cuda_runtime.h>
#include <cuda_bf16.h>
#include <math.h>
#include <cstdint>

#define NHH 12
#define DKK 64
#define DVV 128
#define BB  4
#define LL  2048
#define HH  1024
#define KD  768
#define VD  1536
#define BL  (BB*LL)
#define NTOT 4608

typedef unsigned long long u64;
typedef unsigned int u32;

#define FMA2(c, a, b) asm("fma.rn.f32x2 %0, %1, %2, %0;" : "+l"(c) : "l"(a), "l"(b))
#define MUL2(d, a, b) asm("mul.rn.f32x2 %0, %1, %2;" : "=l"(d) : "l"(a), "l"(b))
#define DUP2(d, s)    asm("mov.b64 %0, {%1, %1};" : "=l"(d) : "r"(s))
#define UNPK2(lo, hi, v) asm("mov.b64 {%0, %1}, %2;" : "=r"(lo), "=r"(hi) : "l"(v))

__device__ __forceinline__ uint32_t smem_to_u32(const void* p) {
    uint32_t a;
    asm("{ .reg .u64 t; cvta.to.shared.u64 t, %1; cvt.u32.u64 %0, t; }" : "=r"(a) : "l"(p));
    return a;
}

#define LDSM4(r0, r1, r2, r3, addr) \
    asm volatile("ldmatrix.sync.aligned.m8n8.x4.shared.b16 {%0,%1,%2,%3}, [%4];" \
        : "=r"(r0), "=r"(r1), "=r"(r2), "=r"(r3) : "r"(addr))

#define MMA16816(c, a, b0, b1) \
    asm volatile("mma.sync.aligned.m16n8k16.row.col.f32.bf16.bf16.f32 " \
        "{%0,%1,%2,%3},{%4,%5,%6,%7},{%8,%9},{%0,%1,%2,%3};" \
        : "+f"((c)[0]), "+f"((c)[1]), "+f"((c)[2]), "+f"((c)[3]) \
        : "r"((a)[0]), "r"((a)[1]), "r"((a)[2]), "r"((a)[3]), "r"(b0), "r"(b1))

__device__ __forceinline__ void cpa16(uint32_t saddr, const void* g) {
    asm volatile("cp.async.cg.shared.global [%0], [%1], 16;" :: "r"(saddr), "l"(g));
}
#define CP_COMMIT() asm volatile("cp.async.commit_group;" ::: "memory")
#define CP_WAIT1()  asm volatile("cp.async.wait_group 1;" ::: "memory")
#define CP_WAIT0()  asm volatile("cp.async.wait_group 0;" ::: "memory")

// ================= scratch =================
__device__ float g_qkvg[(size_t)BL * NTOT];
__device__ __nv_bfloat16 g_hsh[(size_t)BL * HH], g_hsl[(size_t)BL * HH];
__device__ __nv_bfloat16 g_wth[(size_t)NTOT * HH], g_wtl[(size_t)NTOT * HH];
__device__ __nv_bfloat16 g_woth[(size_t)HH * VD], g_wotl[(size_t)HH * VD];
__device__ __nv_bfloat16 g_oh[(size_t)BL * VD], g_ol[(size_t)BL * VD];
__device__ float g_bufQc[BL*KD], g_bufKc[BL*KD], g_bufVc[BL*VD], g_bufO[BL*VD];
__device__ float g_gk[BL*NHH], g_beta[BL*NHH];

// ================= hi/lo split =================
__global__ void split_kernel(const float* __restrict__ in,
                             __nv_bfloat16* __restrict__ oh, __nv_bfloat16* __restrict__ ol, int n) {
    int i = blockIdx.x * 256 + threadIdx.x;
    if (i >= n) return;
    float x = in[i];
    __nv_bfloat16 h = __float2bfloat16(x);
    oh[i] = h;
    ol[i] = __float2bfloat16(x - __bfloat162float(h));
}

// transpose + split: W[K,N] fp32 -> Th/Tl[N,K] bf16
__global__ void transp_split(const float* __restrict__ W, int K, int N,
                             __nv_bfloat16* __restrict__ Th, __nv_bfloat16* __restrict__ Tl) {
    __shared__ float tile[32][33];
    int n0 = blockIdx.x * 32, k0 = blockIdx.y * 32;
    for (int i = threadIdx.y; i < 32; i += 8)
        tile[i][threadIdx.x] = W[(size_t)(k0 + i) * N + n0 + threadIdx.x];
    __syncthreads();
    for (int i = threadIdx.y; i < 32; i += 8) {
        float x = tile[threadIdx.x][i];
        __nv_bfloat16 h = __float2bfloat16(x);
        size_t o = (size_t)(n0 + i) * K + k0 + threadIdx.x;
        Th[o] = h;
        Tl[o] = __float2bfloat16(x - __bfloat162float(h));
    }
}

// ================= mma.sync split-bf16 GEMM =================
#define TILE_B 10240
#define SMEM_GEMM (8 * TILE_B)

__global__ void __launch_bounds__(256)
gemm_mma(const __nv_bfloat16* __restrict__ Ahi, const __nv_bfloat16* __restrict__ Alo,
         const __nv_bfloat16* __restrict__ Bhi, const __nv_bfloat16* __restrict__ Blo,
         float* __restrict__ C, int Kdim, int ldc) {
    extern __shared__ char smem[];
    const uint32_t smb = smem_to_u32(smem);
    const int tid = threadIdx.x;
    const int lane = tid & 31, w = tid >> 5;
    const int wm = (w & 1) * 64, wn = (w >> 1) * 32;
    const int m0 = blockIdx.y * 128, n0 = blockIdx.x * 128;

    const int rL = tid >> 1;
    const int qL = (tid & 1) * 2;

    float c[4][4][4];
#pragma unroll
    for (int i = 0; i < 4; i++)
#pragma unroll
        for (int j = 0; j < 4; j++)
#pragma unroll
            for (int e = 0; e < 4; e++) c[i][j][e] = 0.f;

    const int nCh = Kdim >> 5;

    auto load_stage = [&](int kc, int st) {
        const __nv_bfloat16* a0 = Ahi + (size_t)(m0 + rL) * Kdim + kc * 32 + qL * 8;
        const __nv_bfloat16* a1 = Alo + (size_t)(m0 + rL) * Kdim + kc * 32 + qL * 8;
        const __nv_bfloat16* b0 = Bhi + (size_t)(n0 + rL) * Kdim + kc * 32 + qL * 8;
        const __nv_bfloat16* b1 = Blo + (size_t)(n0 + rL) * Kdim + kc * 32 + qL * 8;
        uint32_t sa0 = smb + (st * 2 + 0) * TILE_B + rL * 80 + qL * 16;
        uint32_t sa1 = smb + (st * 2 + 1) * TILE_B + rL * 80 + qL * 16;
        uint32_t sb0 = smb + 4 * TILE_B + (st * 2 + 0) * TILE_B + rL * 80 + qL * 16;
        uint32_t sb1 = smb + 4 * TILE_B + (st * 2 + 1) * TILE_B + rL * 80 + qL * 16;
        cpa16(sa0, a0); cpa16(sa0 + 16, a0 + 8);
        cpa16(sa1, a1); cpa16(sa1 + 16, a1 + 8);
        cpa16(sb0, b0); cpa16(sb0 + 16, b0 + 8);
        cpa16(sb1, b1); cpa16(sb1 + 16, b1 + 8);
        CP_COMMIT();
    };

    load_stage(0, 0);

    for (int kc = 0; kc < nCh; kc++) {
        const int st = kc & 1;
        const bool has_next = (kc + 1) < nCh;
        if (has_next) load_stage(kc + 1, st ^ 1);
        if (has_next) CP_WAIT1(); else CP_WAIT0();
        __syncthreads();

        const int lrow = lane & 15;
        const int lcolB = ((lane >> 4) << 3) * 2;
#pragma unroll
        for (int ks = 0; ks < 2; ks++) {
            const int kbB = ks * 32 + lcolB;
            uint32_t ah[4][4], al[4][4];
#pragma unroll
            for (int mt = 0; mt < 4; mt++) {
                int row = wm + mt * 16 + lrow;
                uint32_t ad = smb + st * 2 * TILE_B + row * 80 + kbB;
                LDSM4(ah[mt][0], ah[mt][1], ah[mt][2], ah[mt][3], ad);
                LDSM4(al[mt][0], al[mt][1], al[mt][2], al[mt][3], ad + TILE_B);
            }
            uint32_t bh[2][4], bl[2][4];
#pragma unroll
            for (int np = 0; np < 2; np++) {
                int row = wn + np * 16 + lrow;
                uint32_t bd = smb + 4 * TILE_B + st * 2 * TILE_B + row * 80 + kbB;
                LDSM4(bh[np][0], bh[np][1], bh[np][2], bh[np][3], bd);
                LDSM4(bl[np][0], bl[np][1], bl[np][2], bl[np][3], bd + TILE_B);
            }
#pragma unroll
            for (int mt = 0; mt < 4; mt++)
#pragma unroll
                for (int nt = 0; nt < 4; nt++) {
                    int np = nt >> 1, s = nt & 1;
                    MMA16816(c[mt][nt], ah[mt], bh[np][s], bh[np][s + 2]);
                    MMA16816(c[mt][nt], ah[mt], bl[np][s], bl[np][s + 2]);
                    MMA16816(c[mt][nt], al[mt], bh[np][s], bh[np][s + 2]);
                }
        }
        __syncthreads();
    }

#pragma unroll
    for (int mt = 0; mt < 4; mt++) {
        int row = m0 + wm + mt * 16 + (lane >> 2);
#pragma unroll
        for (int nt = 0; nt < 4; nt++) {
            int col = n0 + wn + nt * 8 + (lane & 3) * 2;
            *(float2*)(C + (size_t)row * ldc + col)       = make_float2(c[mt][nt][0], c[mt][nt][1]);
            *(float2*)(C + (size_t)(row + 8) * ldc + col) = make_float2(c[mt][nt][2], c[mt][nt][3]);
        }
    }
}

// ================= gk / beta projection =================
__global__ void gkbeta2(const float* __restrict__ hs,
                        const float* __restrict__ Wgk, const float* __restrict__ Wb,
                        const float* __restrict__ bb,  const float* __restrict__ A_log,
                        const float* __restrict__ dt_bias,
                        float* __restrict__ gk, float* __restrict__ beta) {
    __shared__ float sh[8][HH];
    int w = threadIdx.x >> 5, lane = threadIdx.x & 31;
    int row = blockIdx.x * 8 + w;
    const float* hr = hs + (size_t)row * HH;
    for (int i = lane; i < HH; i += 32) sh[w][i] = hr[i];
    __syncwarp();
    if (lane < 24) {
        const float* W = (lane < 12) ? Wgk : Wb;
        int j = (lane < 12) ? lane : lane - 12;
        float acc = 0.f;
#pragma unroll 4
        for (int k = 0; k < HH; k++) acc += sh[w][k] * W[k * NHH + j];
        if (lane < 12) {
            acc += dt_bias[j];
            float sp = (acc > 20.f) ? acc : log1pf(expf(acc));
            gk[row * NHH + j] = -expf(A_log[j]) * sp;
        } else {
            acc += bb[j];
            beta[row * NHH + j] = 1.f / (1.f + expf(-acc));
        }
    }
}

// ================= conv + silu + l2norm (q & k fused in one launch) =================
__global__ void conv_silu_l2qk(const float* __restrict__ qkvg,
                               const float* __restrict__ wq, const float* __restrict__ wk,
                               float* __restrict__ outq, float* __restrict__ outk) {
    int idx = blockIdx.x;
    int which = idx & 1;             // 0 = q, 1 = k
    idx >>= 1;
    int h  = idx % NHH;
    int bl = idx / NHH;
    int l  = bl % LL;
    int c  = h * DKK + threadIdx.x;
    const float* in = qkvg + (which ? 768 : 0);
    const float* wr = (which ? wk : wq) + c * 4;
    float* out = which ? outk : outq;
    float acc = 0.f;
#pragma unroll
    for (int j = 0; j < 4; j++) {
        int tt = l - 3 + j;
        if (tt >= 0) acc += in[(size_t)(bl - l + tt) * NTOT + c] * wr[j];
    }
    float sv = acc / (1.f + expf(-acc));
    float ss = sv * sv;
#pragma unroll
    for (int off = 16; off; off >>= 1) ss += __shfl_xor_sync(0xffffffffu, ss, off);
    __shared__ float sred[2];
    if ((threadIdx.x & 31) == 0) sred[threadIdx.x >> 5] = ss;
    __syncthreads();
    float n = sqrtf(sred[0] + sred[1]);
    out[(size_t)bl * KD + c] = sv / fmaxf(n, 1e-12f);
}

__global__ void conv_silu_v(const float* __restrict__ in, int istride,
                            const float* __restrict__ w, float* __restrict__ out, int total) {
    int gid = blockIdx.x * blockDim.x + threadIdx.x;
    if (gid >= total) return;
    int c  = gid % VD;
    int bl = gid / VD;
    int l  = bl % LL;
    const float* wr = w + c * 4;
    float acc = 0.f;
#pragma unroll
    for (int j = 0; j < 4; j++) {
        int tt = l - 3 + j;
        if (tt >= 0) acc += in[(size_t)(bl - l + tt) * istride + c] * wr[j];
    }
    out[gid] = acc / (1.f + expf(-acc));
}

// ================= recurrence v3: 256 thr, DK 4-way split =================
// grid = B*NH*2 (64 V-cols per CTA); col = tid>>2, qtr = tid&3 (16 DK each).
// k/q quarters at stride 18 floats in smem -> conflict-free LDS.64.
#define QSTR 18
__global__ void __launch_bounds__(256)
recur3(const float* __restrict__ q, const float* __restrict__ k,
       const float* __restrict__ v, const float* __restrict__ gk,
       const float* __restrict__ beta, float* __restrict__ o) {
    int blk = blockIdx.x;
    int b  = blk / (NHH * 2);
    int h  = (blk >> 1) % NHH;
    int vh = blk & 1;
    int tid = threadIdx.x;
    int col = tid >> 2;
    int qtr = tid & 3;

    __shared__ float ksh[2][4 * QSTR];
    __shared__ float qsh[2][4 * QSTR];
    __shared__ float egsh[LL];
    __shared__ float bsh[LL];

    const float* qb = q + (size_t)b * LL * KD + h * DKK;
    const float* kb = k + (size_t)b * LL * KD + h * DKK;
    const float* vb = v + (size_t)b * LL * VD + h * DVV + vh * 64;
    const float* gb = gk + (size_t)b * LL * NHH + h;
    const float* be = beta + (size_t)b * LL * NHH + h;
    float* ob = o + (size_t)b * LL * VD + h * DVV + vh * 64;

    for (int i = tid; i < LL; i += 256) {
        egsh[i] = expf(gb[(size_t)i * NHH]);
        bsh[i]  = be[(size_t)i * NHH];
    }

    u64 S2[8];
#pragma unroll
    for (int i = 0; i < 8; i++) S2[i] = 0ull;

    const int sq  = tid >> 4;        // quarter index for staging (tid<64)
    const int sidx = tid & 15;
    float pk = 0.f;
    if (tid < 128) pk = (tid < 64) ? kb[tid] : qb[tid - 64];
    float pv = vb[col];
    __syncthreads();

    for (int t = 0; t < LL; t++) {
        const int buf = t & 1;
        if (tid < 64)       ksh[buf][sq * QSTR + sidx] = pk;
        else if (tid < 128) qsh[buf][(sq - 4) * QSTR + sidx] = pk;
        float vv = pv;
        __syncthreads();

        if (t + 1 < LL) {
            if (tid < 128)
                pk = (tid < 64) ? kb[(size_t)(t + 1) * KD + tid]
                                : qb[(size_t)(t + 1) * KD + tid - 64];
            pv = vb[(size_t)(t + 1) * VD + col];
        }

        float eg = egsh[t], bt = bsh[t];
        const u64* kh2 = (const u64*)&ksh[buf][qtr * QSTR];
        const u64* qh2 = (const u64*)&qsh[buf][qtr * QSTR];

        u64 eg2; DUP2(eg2, __float_as_uint(eg));
        u64 p0 = 0ull, p1 = 0ull;
#pragma unroll
        for (int j = 0; j < 8; j += 2) {
            MUL2(S2[j],     S2[j],     eg2);
            MUL2(S2[j + 1], S2[j + 1], eg2);
            FMA2(p0, kh2[j],     S2[j]);
            FMA2(p1, kh2[j + 1], S2[j + 1]);
        }
        u32 plo, phi, plo2, phi2;
        UNPK2(plo, phi, p0);
        UNPK2(plo2, phi2, p1);
        float pred = (__uint_as_float(plo) + __uint_as_float(phi))
                   + (__uint_as_float(plo2) + __uint_as_float(phi2));
        pred += __shfl_xor_sync(0xffffffffu, pred, 1);
        pred += __shfl_xor_sync(0xffffffffu, pred, 2);
        float delta = bt * (vv - pred);

        u64 d2; DUP2(d2, __float_as_uint(delta));
        u64 o0 = 0ull, o1 = 0ull;
#pragma unroll
        for (int j = 0; j < 8; j += 2) {
            FMA2(S2[j],     kh2[j],     d2);
            FMA2(S2[j + 1], kh2[j + 1], d2);
            FMA2(o0, qh2[j],     S2[j]);
            FMA2(o1, qh2[j + 1], S2[j + 1]);
        }
        u32 olo, ohi, olo2, ohi2;
        UNPK2(olo, ohi, o0);
        UNPK2(olo2, ohi2, o1);
        float out = (__uint_as_float(olo) + __uint_as_float(ohi))
                  + (__uint_as_float(olo2) + __uint_as_float(ohi2));
        out += __shfl_xor_sync(0xffffffffu, out, 1);
        out += __shfl_xor_sync(0xffffffffu, out, 2);
        if (qtr == 0) ob[(size_t)t * VD + col] = out;
    }
}

// ================= rmsnorm * gnorm_w * silu(g) -> hi/lo bf16 =================
__global__ void rmsgate_kernel(const float* __restrict__ o, const float* __restrict__ g,
                               const float* __restrict__ gw,
                               __nv_bfloat16* __restrict__ oh, __nv_bfloat16* __restrict__ ol) {
    int bl = blockIdx.x / NHH, h = blockIdx.x % NHH;
    size_t obase = (size_t)blockIdx.x * DVV;
    size_t gbase = (size_t)bl * NTOT + h * DVV;
    int tid = threadIdx.x;
    float val = o[obase + tid];
    float ss = val * val;
#pragma unroll
    for (int off = 16; off; off >>= 1) ss += __shfl_xor_sync(0xffffffffu, ss, off);
    __shared__ float sr[4];
    if ((tid & 31) == 0) sr[tid >> 5] = ss;
    __syncthreads();
    float tot = sr[0] + sr[1] + sr[2] + sr[3];
    float r = rsqrtf(tot / DVV + 1e-5f);
    float gv = g[gbase + tid];
    float sgt = gv / (1.f + expf(-gv));
    float res = val * r * gw[tid] * sgt;
    __nv_bfloat16 hi = __float2bfloat16(res);
    oh[obase + tid] = hi;
    ol[obase + tid] = __float2bfloat16(res - __bfloat162float(hi));
}

// ================= launch =================
extern "C" void kernel_launch(void* const* d_in, const int* in_sizes, int n_in,
                              void* d_out, int out_size) {
    const float *hs = 0, *Wq = 0, *Wk = 0, *Wv = 0, *Wg = 0, *Wgk = 0, *Wb = 0,
                *bbp = 0, *convq = 0, *convk = 0, *convv = 0, *Alog = 0,
                *dtb = 0, *gnw = 0, *Wo = 0;
    int c786 = 0, c1572 = 0, c12288 = 0, c12 = 0, c3072 = 0;
    for (int i = 0; i < n_in; i++) {
        const float* p = (const float*)d_in[i];
        switch (in_sizes[i]) {
            case 8388608: hs = p; break;
            case 786432:  if (c786++ == 0) Wq = p; else Wk = p; break;
            case 1572864: { int j = c1572++; if (j == 0) Wv = p; else if (j == 1) Wg = p; else Wo = p; } break;
            case 12288:   if (c12288++ == 0) Wgk = p; else Wb = p; break;
            case 12:      { int j = c12++; if (j == 0) bbp = p; else if (j == 1) Alog = p; else dtb = p; } break;
            case 3072:    if (c3072++ == 0) convq = p; else convk = p; break;
            case 6144:    convv = p; break;
            case 128:     gnw = p; break;
            default: break;
        }
    }

    float *qkvg, *bQc, *bKc, *bVc, *bO, *bgk, *bbe;
    __nv_bfloat16 *hsh, *hsl, *wth, *wtl, *woth, *wotl, *oh, *ol;
    cudaGetSymbolAddress((void**)&qkvg, g_qkvg);
    cudaGetSymbolAddress((void**)&hsh,  g_hsh);
    cudaGetSymbolAddress((void**)&hsl,  g_hsl);
    cudaGetSymbolAddress((void**)&wth,  g_wth);
    cudaGetSymbolAddress((void**)&wtl,  g_wtl);
    cudaGetSymbolAddress((void**)&woth, g_woth);
    cudaGetSymbolAddress((void**)&wotl, g_wotl);
    cudaGetSymbolAddress((void**)&oh,   g_oh);
    cudaGetSymbolAddress((void**)&ol,   g_ol);
    cudaGetSymbolAddress((void**)&bQc,  g_bufQc);
    cudaGetSymbolAddress((void**)&bKc,  g_bufKc);
    cudaGetSymbolAddress((void**)&bVc,  g_bufVc);
    cudaGetSymbolAddress((void**)&bO,   g_bufO);
    cudaGetSymbolAddress((void**)&bgk,  g_gk);
    cudaGetSymbolAddress((void**)&bbe,  g_beta);

    cudaFuncSetAttribute(gemm_mma, cudaFuncAttributeMaxDynamicSharedMemorySize, SMEM_GEMM);

    // 1) hi/lo splits + weight transposes (Wo early so gemm_mma lands on ncu capture slot)
    split_kernel<<<(BL * HH + 255) / 256, 256>>>(hs, hsh, hsl, BL * HH);
    transp_split<<<dim3(KD / 32, HH / 32), dim3(32, 8)>>>(Wq, HH, KD, wth, wtl);
    transp_split<<<dim3(KD / 32, HH / 32), dim3(32, 8)>>>(Wk, HH, KD, wth + (size_t)768 * HH, wtl + (size_t)768 * HH);
    transp_split<<<dim3(VD / 32, HH / 32), dim3(32, 8)>>>(Wv, HH, VD, wth + (size_t)1536 * HH, wtl + (size_t)1536 * HH);
    transp_split<<<dim3(VD / 32, HH / 32), dim3(32, 8)>>>(Wg, HH, VD, wth + (size_t)3072 * HH, wtl + (size_t)3072 * HH);
    transp_split<<<dim3(HH / 32, VD / 32), dim3(32, 8)>>>(Wo, VD, HH, woth, wotl);

    // 2) fused QKVG projection on tensor cores
    gemm_mma<<<dim3(NTOT / 128, BL / 128), 256, SMEM_GEMM>>>(hsh, hsl, wth, wtl, qkvg, HH, NTOT);

    // 3) gk / beta
    gkbeta2<<<BL / 8, 256>>>(hs, Wgk, Wb, bbp, Alog, dtb, bgk, bbe);

    // 4) conv + silu (+ l2norm for q,k)
    conv_silu_l2qk<<<BL * NHH * 2, 64>>>(qkvg, convq, convk, bQc, bKc);
    int totv = BL * VD;
    conv_silu_v<<<(totv + 255) / 256, 256>>>(qkvg + 1536, NTOT, convv, bVc, totv);

    // 5) recurrence
    recur3<<<BB * NHH * 2, 256>>>(bQc, bKc, bVc, bgk, bbe, bO);

    // 6) rmsnorm + swish gate -> hi/lo bf16
    rmsgate_kernel<<<BL * NHH, 128>>>(bO, qkvg + 3072, gnw, oh, ol);

    // 7) output projection on tensor cores
    gemm_mma<<<dim3(HH / 128, BL / 128), 256, SMEM_GEMM>>>(oh, ol, woth, wotl, (float*)d_out, VD, HH);
}

// round 7
// speedup vs baseline: 2.9148x; 1.4481x over previous
#include <cuda_runtime.h>
#include <cuda_bf16.h>
#include <math.h>
#include <cstdint>

#define NHH 12
#define DKK 64
#define DVV 128
#define BB  4
#define LL  2048
#define HH  1024
#define KD  768
#define VD  1536
#define BL  (BB*LL)
#define NTOT 4608

typedef unsigned long long u64;
typedef unsigned int u32;

#define FMA2(c, a, b) asm("fma.rn.f32x2 %0, %1, %2, %0;" : "+l"(c) : "l"(a), "l"(b))
#define MUL2(d, a, b) asm("mul.rn.f32x2 %0, %1, %2;" : "=l"(d) : "l"(a), "l"(b))
#define DUP2(d, s)    asm("mov.b64 %0, {%1, %1};" : "=l"(d) : "r"(s))
#define UNPK2(lo, hi, v) asm("mov.b64 {%0, %1}, %2;" : "=r"(lo), "=r"(hi) : "l"(v))

__device__ __forceinline__ uint32_t smem_to_u32(const void* p) {
    uint32_t a;
    asm("{ .reg .u64 t; cvta.to.shared.u64 t, %1; cvt.u32.u64 %0, t; }" : "=r"(a) : "l"(p));
    return a;
}

#define LDSM4(r0, r1, r2, r3, addr) \
    asm volatile("ldmatrix.sync.aligned.m8n8.x4.shared.b16 {%0,%1,%2,%3}, [%4];" \
        : "=r"(r0), "=r"(r1), "=r"(r2), "=r"(r3) : "r"(addr))

#define MMA16816(c, a, b0, b1) \
    asm volatile("mma.sync.aligned.m16n8k16.row.col.f32.bf16.bf16.f32 " \
        "{%0,%1,%2,%3},{%4,%5,%6,%7},{%8,%9},{%0,%1,%2,%3};" \
        : "+f"((c)[0]), "+f"((c)[1]), "+f"((c)[2]), "+f"((c)[3]) \
        : "r"((a)[0]), "r"((a)[1]), "r"((a)[2]), "r"((a)[3]), "r"(b0), "r"(b1))

__device__ __forceinline__ void cpa16(uint32_t saddr, const void* g) {
    asm volatile("cp.async.cg.shared.global [%0], [%1], 16;" :: "r"(saddr), "l"(g));
}
#define CP_COMMIT() asm volatile("cp.async.commit_group;" ::: "memory")
#define CP_WAIT1()  asm volatile("cp.async.wait_group 1;" ::: "memory")
#define CP_WAIT0()  asm volatile("cp.async.wait_group 0;" ::: "memory")

// ================= scratch =================
__device__ float g_qkvg[(size_t)BL * NTOT];
__device__ __nv_bfloat16 g_hsh[(size_t)BL * HH], g_hsl[(size_t)BL * HH];
__device__ __nv_bfloat16 g_wth[(size_t)NTOT * HH], g_wtl[(size_t)NTOT * HH];
__device__ __nv_bfloat16 g_woth[(size_t)HH * VD], g_wotl[(size_t)HH * VD];
__device__ __nv_bfloat16 g_oh[(size_t)BL * VD], g_ol[(size_t)BL * VD];
__device__ float g_bufQc[BL*KD], g_bufKc[BL*KD], g_bufVc[BL*VD], g_bufO[BL*VD];
__device__ float g_gk[BL*NHH], g_beta[BL*NHH];

// ================= hi/lo split =================
__global__ void split_kernel(const float* __restrict__ in,
                             __nv_bfloat16* __restrict__ oh, __nv_bfloat16* __restrict__ ol, int n) {
    int i = blockIdx.x * 256 + threadIdx.x;
    if (i >= n) return;
    float x = in[i];
    __nv_bfloat16 h = __float2bfloat16(x);
    oh[i] = h;
    ol[i] = __float2bfloat16(x - __bfloat162float(h));
}

// transpose + split: W[K,N] fp32 -> Th/Tl[N,K] bf16
__global__ void transp_split(const float* __restrict__ W, int K, int N,
                             __nv_bfloat16* __restrict__ Th, __nv_bfloat16* __restrict__ Tl) {
    __shared__ float tile[32][33];
    int n0 = blockIdx.x * 32, k0 = blockIdx.y * 32;
    for (int i = threadIdx.y; i < 32; i += 8)
        tile[i][threadIdx.x] = W[(size_t)(k0 + i) * N + n0 + threadIdx.x];
    __syncthreads();
    for (int i = threadIdx.y; i < 32; i += 8) {
        float x = tile[threadIdx.x][i];
        __nv_bfloat16 h = __float2bfloat16(x);
        size_t o = (size_t)(n0 + i) * K + k0 + threadIdx.x;
        Th[o] = h;
        Tl[o] = __float2bfloat16(x - __bfloat162float(h));
    }
}

// ================= mma.sync split-bf16 GEMM (2 CTA/SM) =================
#define TILE_B 10240
#define SMEM_GEMM (8 * TILE_B)

__global__ void __launch_bounds__(256, 2)
gemm_mma(const __nv_bfloat16* __restrict__ Ahi, const __nv_bfloat16* __restrict__ Alo,
         const __nv_bfloat16* __restrict__ Bhi, const __nv_bfloat16* __restrict__ Blo,
         float* __restrict__ C, int Kdim, int ldc) {
    extern __shared__ char smem[];
    const uint32_t smb = smem_to_u32(smem);
    const int tid = threadIdx.x;
    const int lane = tid & 31, w = tid >> 5;
    const int wm = (w & 1) * 64, wn = (w >> 1) * 32;
    const int m0 = blockIdx.y * 128, n0 = blockIdx.x * 128;

    const int rL = tid >> 1;
    const int qL = (tid & 1) * 2;

    float c[4][4][4];
#pragma unroll
    for (int i = 0; i < 4; i++)
#pragma unroll
        for (int j = 0; j < 4; j++)
#pragma unroll
            for (int e = 0; e < 4; e++) c[i][j][e] = 0.f;

    const int nCh = Kdim >> 5;

    auto load_stage = [&](int kc, int st) {
        const __nv_bfloat16* a0 = Ahi + (size_t)(m0 + rL) * Kdim + kc * 32 + qL * 8;
        const __nv_bfloat16* a1 = Alo + (size_t)(m0 + rL) * Kdim + kc * 32 + qL * 8;
        const __nv_bfloat16* b0 = Bhi + (size_t)(n0 + rL) * Kdim + kc * 32 + qL * 8;
        const __nv_bfloat16* b1 = Blo + (size_t)(n0 + rL) * Kdim + kc * 32 + qL * 8;
        uint32_t sa0 = smb + (st * 2 + 0) * TILE_B + rL * 80 + qL * 16;
        uint32_t sa1 = smb + (st * 2 + 1) * TILE_B + rL * 80 + qL * 16;
        uint32_t sb0 = smb + 4 * TILE_B + (st * 2 + 0) * TILE_B + rL * 80 + qL * 16;
        uint32_t sb1 = smb + 4 * TILE_B + (st * 2 + 1) * TILE_B + rL * 80 + qL * 16;
        cpa16(sa0, a0); cpa16(sa0 + 16, a0 + 8);
        cpa16(sa1, a1); cpa16(sa1 + 16, a1 + 8);
        cpa16(sb0, b0); cpa16(sb0 + 16, b0 + 8);
        cpa16(sb1, b1); cpa16(sb1 + 16, b1 + 8);
        CP_COMMIT();
    };

    load_stage(0, 0);

    for (int kc = 0; kc < nCh; kc++) {
        const int st = kc & 1;
        const bool has_next = (kc + 1) < nCh;
        if (has_next) load_stage(kc + 1, st ^ 1);
        if (has_next) CP_WAIT1(); else CP_WAIT0();
        __syncthreads();

        const int lrow = lane & 15;
        const int lcolB = ((lane >> 4) << 3) * 2;
#pragma unroll
        for (int ks = 0; ks < 2; ks++) {
            const int kbB = ks * 32 + lcolB;
            uint32_t bh[2][4], bl[2][4];
#pragma unroll
            for (int np = 0; np < 2; np++) {
                int row = wn + np * 16 + lrow;
                uint32_t bd = smb + 4 * TILE_B + st * 2 * TILE_B + row * 80 + kbB;
                LDSM4(bh[np][0], bh[np][1], bh[np][2], bh[np][3], bd);
                LDSM4(bl[np][0], bl[np][1], bl[np][2], bl[np][3], bd + TILE_B);
            }
#pragma unroll
            for (int mt = 0; mt < 4; mt++) {
                uint32_t ah[4], al[4];
                int row = wm + mt * 16 + lrow;
                uint32_t ad = smb + st * 2 * TILE_B + row * 80 + kbB;
                LDSM4(ah[0], ah[1], ah[2], ah[3], ad);
                LDSM4(al[0], al[1], al[2], al[3], ad + TILE_B);
#pragma unroll
                for (int nt = 0; nt < 4; nt++) {
                    int np = nt >> 1, s = nt & 1;
                    MMA16816(c[mt][nt], ah, bh[np][s], bh[np][s + 2]);
                    MMA16816(c[mt][nt], ah, bl[np][s], bl[np][s + 2]);
                    MMA16816(c[mt][nt], al, bh[np][s], bh[np][s + 2]);
                }
            }
        }
        __syncthreads();
    }

#pragma unroll
    for (int mt = 0; mt < 4; mt++) {
        int row = m0 + wm + mt * 16 + (lane >> 2);
#pragma unroll
        for (int nt = 0; nt < 4; nt++) {
            int col = n0 + wn + nt * 8 + (lane & 3) * 2;
            *(float2*)(C + (size_t)row * ldc + col)       = make_float2(c[mt][nt][0], c[mt][nt][1]);
            *(float2*)(C + (size_t)(row + 8) * ldc + col) = make_float2(c[mt][nt][2], c[mt][nt][3]);
        }
    }
}

// ================= gk / beta projection =================
__global__ void gkbeta2(const float* __restrict__ hs,
                        const float* __restrict__ Wgk, const float* __restrict__ Wb,
                        const float* __restrict__ bb,  const float* __restrict__ A_log,
                        const float* __restrict__ dt_bias,
                        float* __restrict__ gk, float* __restrict__ beta) {
    __shared__ float sh[8][HH];
    int w = threadIdx.x >> 5, lane = threadIdx.x & 31;
    int row = blockIdx.x * 8 + w;
    const float* hr = hs + (size_t)row * HH;
    for (int i = lane; i < HH; i += 32) sh[w][i] = hr[i];
    __syncwarp();
    if (lane < 24) {
        const float* W = (lane < 12) ? Wgk : Wb;
        int j = (lane < 12) ? lane : lane - 12;
        float acc = 0.f;
#pragma unroll 4
        for (int k = 0; k < HH; k++) acc += sh[w][k] * W[k * NHH + j];
        if (lane < 12) {
            acc += dt_bias[j];
            float sp = (acc > 20.f) ? acc : log1pf(expf(acc));
            gk[row * NHH + j] = -expf(A_log[j]) * sp;
        } else {
            acc += bb[j];
            beta[row * NHH + j] = 1.f / (1.f + expf(-acc));
        }
    }
}

// ================= conv + silu + l2norm (q & k in one launch) =================
__global__ void conv_silu_l2qk(const float* __restrict__ qkvg,
                               const float* __restrict__ wq, const float* __restrict__ wk,
                               float* __restrict__ outq, float* __restrict__ outk) {
    int idx = blockIdx.x;
    int which = idx & 1;
    idx >>= 1;
    int h  = idx % NHH;
    int bl = idx / NHH;
    int l  = bl % LL;
    int c  = h * DKK + threadIdx.x;
    const float* in = qkvg + (which ? 768 : 0);
    const float* wr = (which ? wk : wq) + c * 4;
    float* out = which ? outk : outq;
    float acc = 0.f;
#pragma unroll
    for (int j = 0; j < 4; j++) {
        int tt = l - 3 + j;
        if (tt >= 0) acc += in[(size_t)(bl - l + tt) * NTOT + c] * wr[j];
    }
    float sv = acc / (1.f + expf(-acc));
    float ss = sv * sv;
#pragma unroll
    for (int off = 16; off; off >>= 1) ss += __shfl_xor_sync(0xffffffffu, ss, off);
    __shared__ float sred[2];
    if ((threadIdx.x & 31) == 0) sred[threadIdx.x >> 5] = ss;
    __syncthreads();
    float n = sqrtf(sred[0] + sred[1]);
    out[(size_t)bl * KD + c] = sv / fmaxf(n, 1e-12f);
}

__global__ void conv_silu_v(const float* __restrict__ in, int istride,
                            const float* __restrict__ w, float* __restrict__ out, int total) {
    int gid = blockIdx.x * blockDim.x + threadIdx.x;
    if (gid >= total) return;
    int c  = gid % VD;
    int bl = gid / VD;
    int l  = bl % LL;
    const float* wr = w + c * 4;
    float acc = 0.f;
#pragma unroll
    for (int j = 0; j < 4; j++) {
        int tt = l - 3 + j;
        if (tt >= 0) acc += in[(size_t)(bl - l + tt) * istride + c] * wr[j];
    }
    out[gid] = acc / (1.f + expf(-acc));
}

// ================= recurrence v4: 8-step groups, 1 barrier/group =================
// grid = B*NH*2, 128 threads; col = tid>>1 (64 V cols), half = tid&1 (32 DK each).
#define TS 8
__global__ void __launch_bounds__(128)
recur4(const float* __restrict__ q, const float* __restrict__ k,
       const float* __restrict__ v, const float* __restrict__ gk,
       const float* __restrict__ beta, float* __restrict__ o) {
    int blk = blockIdx.x;
    int b  = blk / (NHH * 2);
    int h  = (blk >> 1) % NHH;
    int vh = blk & 1;
    int tid = threadIdx.x;
    int col  = tid >> 1;
    int half = tid & 1;

    __shared__ float ksh[2][TS][64];
    __shared__ float qsh[2][TS][64];
    __shared__ float vsh[2][TS][64];
    __shared__ float egsh[LL];
    __shared__ float bsh[LL];

    const float* qb = q + (size_t)b * LL * KD + h * DKK;
    const float* kb = k + (size_t)b * LL * KD + h * DKK;
    const float* vb = v + (size_t)b * LL * VD + h * DVV + vh * 64;
    const float* gb = gk + (size_t)b * LL * NHH + h;
    const float* be = beta + (size_t)b * LL * NHH + h;
    float* ob = o + (size_t)b * LL * VD + h * DVV + vh * 64;

    for (int i = tid; i < LL; i += 128) {
        egsh[i] = expf(gb[(size_t)i * NHH]);
        bsh[i]  = be[(size_t)i * NHH];
    }

    u64 S2[16];
#pragma unroll
    for (int i = 0; i < 16; i++) S2[i] = 0ull;

    const int ls = tid >> 6;   // 0..1
    const int lc = tid & 63;
#pragma unroll
    for (int i = 0; i < 4; i++) {
        int s = i * 2 + ls;
        ksh[0][s][lc] = kb[(size_t)s * KD + lc];
        qsh[0][s][lc] = qb[(size_t)s * KD + lc];
        vsh[0][s][lc] = vb[(size_t)s * VD + lc];
    }
    __syncthreads();

    const int NG = LL / TS;
    for (int g = 0; g < NG; g++) {
        const int buf = g & 1;
        float rk[4], rq[4], rv[4];
        const bool more = (g + 1) < NG;
        if (more) {
            int t0 = (g + 1) * TS;
#pragma unroll
            for (int i = 0; i < 4; i++) {
                int s = i * 2 + ls;
                rk[i] = kb[(size_t)(t0 + s) * KD + lc];
                rq[i] = qb[(size_t)(t0 + s) * KD + lc];
                rv[i] = vb[(size_t)(t0 + s) * VD + lc];
            }
        }
#pragma unroll
        for (int s = 0; s < TS; s++) {
            int t = g * TS + s;
            float eg = egsh[t], bt = bsh[t];
            float vv = vsh[buf][s][col];
            const u64* kh2 = (const u64*)&ksh[buf][s][half * 32];
            const u64* qh2 = (const u64*)&qsh[buf][s][half * 32];

            u64 eg2; DUP2(eg2, __float_as_uint(eg));
            u64 p0 = 0ull, p1 = 0ull, p2 = 0ull, p3 = 0ull;
#pragma unroll
            for (int j = 0; j < 16; j += 4) {
                MUL2(S2[j],     S2[j],     eg2);
                MUL2(S2[j + 1], S2[j + 1], eg2);
                MUL2(S2[j + 2], S2[j + 2], eg2);
                MUL2(S2[j + 3], S2[j + 3], eg2);
                FMA2(p0, kh2[j],     S2[j]);
                FMA2(p1, kh2[j + 1], S2[j + 1]);
                FMA2(p2, kh2[j + 2], S2[j + 2]);
                FMA2(p3, kh2[j + 3], S2[j + 3]);
            }
            u32 a0, a1, a2, a3, a4, a5, a6, a7;
            UNPK2(a0, a1, p0); UNPK2(a2, a3, p1);
            UNPK2(a4, a5, p2); UNPK2(a6, a7, p3);
            float pred = ((__uint_as_float(a0) + __uint_as_float(a1)) +
                          (__uint_as_float(a2) + __uint_as_float(a3))) +
                         ((__uint_as_float(a4) + __uint_as_float(a5)) +
                          (__uint_as_float(a6) + __uint_as_float(a7)));
            pred += __shfl_xor_sync(0xffffffffu, pred, 1);
            float delta = bt * (vv - pred);

            u64 d2; DUP2(d2, __float_as_uint(delta));
            u64 o0 = 0ull, o1 = 0ull, o2 = 0ull, o3 = 0ull;
#pragma unroll
            for (int j = 0; j < 16; j += 4) {
                FMA2(S2[j],     kh2[j],     d2);
                FMA2(S2[j + 1], kh2[j + 1], d2);
                FMA2(S2[j + 2], kh2[j + 2], d2);
                FMA2(S2[j + 3], kh2[j + 3], d2);
                FMA2(o0, qh2[j],     S2[j]);
                FMA2(o1, qh2[j + 1], S2[j + 1]);
                FMA2(o2, qh2[j + 2], S2[j + 2]);
                FMA2(o3, qh2[j + 3], S2[j + 3]);
            }
            UNPK2(a0, a1, o0); UNPK2(a2, a3, o1);
            UNPK2(a4, a5, o2); UNPK2(a6, a7, o3);
            float out = ((__uint_as_float(a0) + __uint_as_float(a1)) +
                         (__uint_as_float(a2) + __uint_as_float(a3))) +
                        ((__uint_as_float(a4) + __uint_as_float(a5)) +
                         (__uint_as_float(a6) + __uint_as_float(a7)));
            out += __shfl_xor_sync(0xffffffffu, out, 1);
            if (half == 0) ob[(size_t)t * VD + col] = out;
        }
        if (more) {
#pragma unroll
            for (int i = 0; i < 4; i++) {
                int s = i * 2 + ls;
                ksh[buf ^ 1][s][lc] = rk[i];
                qsh[buf ^ 1][s][lc] = rq[i];
                vsh[buf ^ 1][s][lc] = rv[i];
            }
        }
        __syncthreads();
    }
}

// ================= rmsnorm * gnorm_w * silu(g) -> hi/lo bf16 =================
__global__ void rmsgate_kernel(const float* __restrict__ o, const float* __restrict__ g,
                               const float* __restrict__ gw,
                               __nv_bfloat16* __restrict__ oh, __nv_bfloat16* __restrict__ ol) {
    int bl = blockIdx.x / NHH, h = blockIdx.x % NHH;
    size_t obase = (size_t)blockIdx.x * DVV;
    size_t gbase = (size_t)bl * NTOT + h * DVV;
    int tid = threadIdx.x;
    float val = o[obase + tid];
    float ss = val * val;
#pragma unroll
    for (int off = 16; off; off >>= 1) ss += __shfl_xor_sync(0xffffffffu, ss, off);
    __shared__ float sr[4];
    if ((tid & 31) == 0) sr[tid >> 5] = ss;
    __syncthreads();
    float tot = sr[0] + sr[1] + sr[2] + sr[3];
    float r = rsqrtf(tot / DVV + 1e-5f);
    float gv = g[gbase + tid];
    float sgt = gv / (1.f + expf(-gv));
    float res = val * r * gw[tid] * sgt;
    __nv_bfloat16 hi = __float2bfloat16(res);
    oh[obase + tid] = hi;
    ol[obase + tid] = __float2bfloat16(res - __bfloat162float(hi));
}

// ================= launch =================
extern "C" void kernel_launch(void* const* d_in, const int* in_sizes, int n_in,
                              void* d_out, int out_size) {
    const float *hs = 0, *Wq = 0, *Wk = 0, *Wv = 0, *Wg = 0, *Wgk = 0, *Wb = 0,
                *bbp = 0, *convq = 0, *convk = 0, *convv = 0, *Alog = 0,
                *dtb = 0, *gnw = 0, *Wo = 0;
    int c786 = 0, c1572 = 0, c12288 = 0, c12 = 0, c3072 = 0;
    for (int i = 0; i < n_in; i++) {
        const float* p = (const float*)d_in[i];
        switch (in_sizes[i]) {
            case 8388608: hs = p; break;
            case 786432:  if (c786++ == 0) Wq = p; else Wk = p; break;
            case 1572864: { int j = c1572++; if (j == 0) Wv = p; else if (j == 1) Wg = p; else Wo = p; } break;
            case 12288:   if (c12288++ == 0) Wgk = p; else Wb = p; break;
            case 12:      { int j = c12++; if (j == 0) bbp = p; else if (j == 1) Alog = p; else dtb = p; } break;
            case 3072:    if (c3072++ == 0) convq = p; else convk = p; break;
            case 6144:    convv = p; break;
            case 128:     gnw = p; break;
            default: break;
        }
    }

    float *qkvg, *bQc, *bKc, *bVc, *bO, *bgk, *bbe;
    __nv_bfloat16 *hsh, *hsl, *wth, *wtl, *woth, *wotl, *oh, *ol;
    cudaGetSymbolAddress((void**)&qkvg, g_qkvg);
    cudaGetSymbolAddress((void**)&hsh,  g_hsh);
    cudaGetSymbolAddress((void**)&hsl,  g_hsl);
    cudaGetSymbolAddress((void**)&wth,  g_wth);
    cudaGetSymbolAddress((void**)&wtl,  g_wtl);
    cudaGetSymbolAddress((void**)&woth, g_woth);
    cudaGetSymbolAddress((void**)&wotl, g_wotl);
    cudaGetSymbolAddress((void**)&oh,   g_oh);
    cudaGetSymbolAddress((void**)&ol,   g_ol);
    cudaGetSymbolAddress((void**)&bQc,  g_bufQc);
    cudaGetSymbolAddress((void**)&bKc,  g_bufKc);
    cudaGetSymbolAddress((void**)&bVc,  g_bufVc);
    cudaGetSymbolAddress((void**)&bO,   g_bufO);
    cudaGetSymbolAddress((void**)&bgk,  g_gk);
    cudaGetSymbolAddress((void**)&bbe,  g_beta);

    cudaFuncSetAttribute(gemm_mma, cudaFuncAttributeMaxDynamicSharedMemorySize, SMEM_GEMM);

    // launches 1-5: split + QKVG weight transposes
    split_kernel<<<(BL * HH + 255) / 256, 256>>>(hs, hsh, hsl, BL * HH);
    transp_split<<<dim3(KD / 32, HH / 32), dim3(32, 8)>>>(Wq, HH, KD, wth, wtl);
    transp_split<<<dim3(KD / 32, HH / 32), dim3(32, 8)>>>(Wk, HH, KD, wth + (size_t)768 * HH, wtl + (size_t)768 * HH);
    transp_split<<<dim3(VD / 32, HH / 32), dim3(32, 8)>>>(Wv, HH, VD, wth + (size_t)1536 * HH, wtl + (size_t)1536 * HH);
    transp_split<<<dim3(VD / 32, HH / 32), dim3(32, 8)>>>(Wg, HH, VD, wth + (size_t)3072 * HH, wtl + (size_t)3072 * HH);

    // launch 6: QKVG projection (ncu capture slot)
    gemm_mma<<<dim3(NTOT / 128, BL / 128), 256, SMEM_GEMM>>>(hsh, hsl, wth, wtl, qkvg, HH, NTOT);

    transp_split<<<dim3(HH / 32, VD / 32), dim3(32, 8)>>>(Wo, VD, HH, woth, wotl);
    gkbeta2<<<BL / 8, 256>>>(hs, Wgk, Wb, bbp, Alog, dtb, bgk, bbe);
    conv_silu_l2qk<<<BL * NHH * 2, 64>>>(qkvg, convq, convk, bQc, bKc);
    int totv = BL * VD;
    conv_silu_v<<<(totv + 255) / 256, 256>>>(qkvg + 1536, NTOT, convv, bVc, totv);

    recur4<<<BB * NHH * 2, 128>>>(bQc, bKc, bVc, bgk, bbe, bO);
    rmsgate_kernel<<<BL * NHH, 128>>>(bO, qkvg + 3072, gnw, oh, ol);
    gemm_mma<<<dim3(HH / 128, BL / 128), 256, SMEM_GEMM>>>(oh, ol, woth, wotl, (float*)d_out, VD, HH);
}

// round 8
// speedup vs baseline: 2.9588x; 1.0151x over previous
#include <cuda_runtime.h>
#include <cuda_bf16.h>
#include <math.h>
#include <cstdint>

#define NHH 12
#define DKK 64
#define DVV 128
#define BB  4
#define LL  2048
#define HH  1024
#define KD  768
#define VD  1536
#define BL  (BB*LL)
#define NTOT 4608

typedef unsigned long long u64;
typedef unsigned int u32;

#define FMA2(c, a, b) asm("fma.rn.f32x2 %0, %1, %2, %0;" : "+l"(c) : "l"(a), "l"(b))
#define MUL2(d, a, b) asm("mul.rn.f32x2 %0, %1, %2;" : "=l"(d) : "l"(a), "l"(b))
#define DUP2(d, s)    asm("mov.b64 %0, {%1, %1};" : "=l"(d) : "r"(s))
#define UNPK2(lo, hi, v) asm("mov.b64 {%0, %1}, %2;" : "=r"(lo), "=r"(hi) : "l"(v))

__device__ __forceinline__ uint32_t smem_to_u32(const void* p) {
    uint32_t a;
    asm("{ .reg .u64 t; cvta.to.shared.u64 t, %1; cvt.u32.u64 %0, t; }" : "=r"(a) : "l"(p));
    return a;
}

#define LDSM4(r0, r1, r2, r3, addr) \
    asm volatile("ldmatrix.sync.aligned.m8n8.x4.shared.b16 {%0,%1,%2,%3}, [%4];" \
        : "=r"(r0), "=r"(r1), "=r"(r2), "=r"(r3) : "r"(addr))

#define MMA16816(c, a, b0, b1) \
    asm volatile("mma.sync.aligned.m16n8k16.row.col.f32.bf16.bf16.f32 " \
        "{%0,%1,%2,%3},{%4,%5,%6,%7},{%8,%9},{%0,%1,%2,%3};" \
        : "+f"((c)[0]), "+f"((c)[1]), "+f"((c)[2]), "+f"((c)[3]) \
        : "r"((a)[0]), "r"((a)[1]), "r"((a)[2]), "r"((a)[3]), "r"(b0), "r"(b1))

__device__ __forceinline__ void cpa16(uint32_t saddr, const void* g) {
    asm volatile("cp.async.cg.shared.global [%0], [%1], 16;" :: "r"(saddr), "l"(g));
}
#define CP_COMMIT() asm volatile("cp.async.commit_group;" ::: "memory")
#define CP_WAIT0()  asm volatile("cp.async.wait_group 0;" ::: "memory")

// ================= scratch =================
__device__ float g_qkvg[(size_t)BL * NTOT];
__device__ __nv_bfloat16 g_hsh[(size_t)BL * HH], g_hsl[(size_t)BL * HH];
__device__ __nv_bfloat16 g_wth[(size_t)NTOT * HH], g_wtl[(size_t)NTOT * HH];
__device__ __nv_bfloat16 g_woth[(size_t)HH * VD], g_wotl[(size_t)HH * VD];
__device__ __nv_bfloat16 g_oh[(size_t)BL * VD], g_ol[(size_t)BL * VD];
__device__ float g_bufQc[BL*KD], g_bufKc[BL*KD], g_bufVc[BL*VD], g_bufO[BL*VD];
__device__ float g_gk[BL*NHH], g_beta[BL*NHH];

// ================= hi/lo split =================
__global__ void split_kernel(const float* __restrict__ in,
                             __nv_bfloat16* __restrict__ oh, __nv_bfloat16* __restrict__ ol, int n) {
    int i = blockIdx.x * 256 + threadIdx.x;
    if (i >= n) return;
    float x = in[i];
    __nv_bfloat16 h = __float2bfloat16(x);
    oh[i] = h;
    ol[i] = __float2bfloat16(x - __bfloat162float(h));
}

// ================= fused transpose+split of all 5 weight matrices =================
// tiles: Wq 24x32=768, Wk 768, Wv 48x32=1536, Wg 1536, Wo 32x48=1536 -> 6144 blocks
__device__ __forceinline__ void transp_tile(const float* __restrict__ W, int K, int N,
                                            __nv_bfloat16* __restrict__ Th,
                                            __nv_bfloat16* __restrict__ Tl,
                                            int n0, int k0, float* tile /*[32][33]*/) {
    int tx = threadIdx.x, ty = threadIdx.y;
    for (int i = ty; i < 32; i += 8)
        tile[i * 33 + tx] = W[(size_t)(k0 + i) * N + n0 + tx];
    __syncthreads();
    for (int i = ty; i < 32; i += 8) {
        float x = tile[tx * 33 + i];
        __nv_bfloat16 h = __float2bfloat16(x);
        size_t o = (size_t)(n0 + i) * K + k0 + tx;
        Th[o] = h;
        Tl[o] = __float2bfloat16(x - __bfloat162float(h));
    }
}

__global__ void transp_all(const float* __restrict__ Wq, const float* __restrict__ Wk,
                           const float* __restrict__ Wv, const float* __restrict__ Wg,
                           const float* __restrict__ Wo,
                           __nv_bfloat16* __restrict__ wth, __nv_bfloat16* __restrict__ wtl,
                           __nv_bfloat16* __restrict__ woth, __nv_bfloat16* __restrict__ wotl) {
    __shared__ float tile[32 * 33];
    int idx = blockIdx.x;
    if (idx < 768) {
        transp_tile(Wq, HH, KD, wth, wtl, (idx % 24) * 32, (idx / 24) * 32, tile);
    } else if (idx < 1536) {
        idx -= 768;
        transp_tile(Wk, HH, KD, wth + (size_t)768 * HH, wtl + (size_t)768 * HH,
                    (idx % 24) * 32, (idx / 24) * 32, tile);
    } else if (idx < 3072) {
        idx -= 1536;
        transp_tile(Wv, HH, VD, wth + (size_t)1536 * HH, wtl + (size_t)1536 * HH,
                    (idx % 48) * 32, (idx / 48) * 32, tile);
    } else if (idx < 4608) {
        idx -= 3072;
        transp_tile(Wg, HH, VD, wth + (size_t)3072 * HH, wtl + (size_t)3072 * HH,
                    (idx % 48) * 32, (idx / 48) * 32, tile);
    } else {
        idx -= 4608;
        transp_tile(Wo, VD, HH, woth, wotl, (idx % 32) * 32, (idx / 32) * 32, tile);
    }
}

// ================= mma.sync split-bf16 GEMM (2 CTA/SM, 1 sync/chunk) =================
#define TILE_B 10240
#define SMEM_GEMM (8 * TILE_B)

__global__ void __launch_bounds__(256, 2)
gemm_mma(const __nv_bfloat16* __restrict__ Ahi, const __nv_bfloat16* __restrict__ Alo,
         const __nv_bfloat16* __restrict__ Bhi, const __nv_bfloat16* __restrict__ Blo,
         float* __restrict__ C, int Kdim, int ldc) {
    extern __shared__ char smem[];
    const uint32_t smb = smem_to_u32(smem);
    const int tid = threadIdx.x;
    const int lane = tid & 31, w = tid >> 5;
    const int wm = (w & 1) * 64, wn = (w >> 1) * 32;
    const int m0 = blockIdx.y * 128, n0 = blockIdx.x * 128;

    const int rL = tid >> 1;
    const int qL = (tid & 1) * 2;

    float c[4][4][4];
#pragma unroll
    for (int i = 0; i < 4; i++)
#pragma unroll
        for (int j = 0; j < 4; j++)
#pragma unroll
            for (int e = 0; e < 4; e++) c[i][j][e] = 0.f;

    const int nCh = Kdim >> 5;

    auto load_stage = [&](int kc, int st) {
        const __nv_bfloat16* a0 = Ahi + (size_t)(m0 + rL) * Kdim + kc * 32 + qL * 8;
        const __nv_bfloat16* a1 = Alo + (size_t)(m0 + rL) * Kdim + kc * 32 + qL * 8;
        const __nv_bfloat16* b0 = Bhi + (size_t)(n0 + rL) * Kdim + kc * 32 + qL * 8;
        const __nv_bfloat16* b1 = Blo + (size_t)(n0 + rL) * Kdim + kc * 32 + qL * 8;
        uint32_t sa0 = smb + (st * 2 + 0) * TILE_B + rL * 80 + qL * 16;
        uint32_t sa1 = smb + (st * 2 + 1) * TILE_B + rL * 80 + qL * 16;
        uint32_t sb0 = smb + 4 * TILE_B + (st * 2 + 0) * TILE_B + rL * 80 + qL * 16;
        uint32_t sb1 = smb + 4 * TILE_B + (st * 2 + 1) * TILE_B + rL * 80 + qL * 16;
        cpa16(sa0, a0); cpa16(sa0 + 16, a0 + 8);
        cpa16(sa1, a1); cpa16(sa1 + 16, a1 + 8);
        cpa16(sb0, b0); cpa16(sb0 + 16, b0 + 8);
        cpa16(sb1, b1); cpa16(sb1 + 16, b1 + 8);
        CP_COMMIT();
    };

    load_stage(0, 0);

    for (int kc = 0; kc < nCh; kc++) {
        const int st = kc & 1;
        CP_WAIT0();
        __syncthreads();
        if (kc + 1 < nCh) load_stage(kc + 1, st ^ 1);

        const int lrow = lane & 15;
        const int lcolB = ((lane >> 4) << 3) * 2;
#pragma unroll
        for (int ks = 0; ks < 2; ks++) {
            const int kbB = ks * 32 + lcolB;
            uint32_t bh[2][4], bl[2][4];
#pragma unroll
            for (int np = 0; np < 2; np++) {
                int row = wn + np * 16 + lrow;
                uint32_t bd = smb + 4 * TILE_B + st * 2 * TILE_B + row * 80 + kbB;
                LDSM4(bh[np][0], bh[np][1], bh[np][2], bh[np][3], bd);
                LDSM4(bl[np][0], bl[np][1], bl[np][2], bl[np][3], bd + TILE_B);
            }
#pragma unroll
            for (int mt = 0; mt < 4; mt++) {
                uint32_t ah[4], al[4];
                int row = wm + mt * 16 + lrow;
                uint32_t ad = smb + st * 2 * TILE_B + row * 80 + kbB;
                LDSM4(ah[0], ah[1], ah[2], ah[3], ad);
                LDSM4(al[0], al[1], al[2], al[3], ad + TILE_B);
#pragma unroll
                for (int nt = 0; nt < 4; nt++) {
                    int np = nt >> 1, s = nt & 1;
                    MMA16816(c[mt][nt], ah, bh[np][s], bh[np][s + 2]);
                    MMA16816(c[mt][nt], ah, bl[np][s], bl[np][s + 2]);
                    MMA16816(c[mt][nt], al, bh[np][s], bh[np][s + 2]);
                }
            }
        }
    }
    CP_WAIT0();

#pragma unroll
    for (int mt = 0; mt < 4; mt++) {
        int row = m0 + wm + mt * 16 + (lane >> 2);
#pragma unroll
        for (int nt = 0; nt < 4; nt++) {
            int col = n0 + wn + nt * 8 + (lane & 3) * 2;
            *(float2*)(C + (size_t)row * ldc + col)       = make_float2(c[mt][nt][0], c[mt][nt][1]);
            *(float2*)(C + (size_t)(row + 8) * ldc + col) = make_float2(c[mt][nt][2], c[mt][nt][3]);
        }
    }
}

// ================= gk / beta projection =================
__global__ void gkbeta2(const float* __restrict__ hs,
                        const float* __restrict__ Wgk, const float* __restrict__ Wb,
                        const float* __restrict__ bb,  const float* __restrict__ A_log,
                        const float* __restrict__ dt_bias,
                        float* __restrict__ gk, float* __restrict__ beta) {
    __shared__ float sh[8][HH];
    int w = threadIdx.x >> 5, lane = threadIdx.x & 31;
    int row = blockIdx.x * 8 + w;
    const float* hr = hs + (size_t)row * HH;
    for (int i = lane; i < HH; i += 32) sh[w][i] = hr[i];
    __syncwarp();
    if (lane < 24) {
        const float* W = (lane < 12) ? Wgk : Wb;
        int j = (lane < 12) ? lane : lane - 12;
        float acc = 0.f;
#pragma unroll 4
        for (int k = 0; k < HH; k++) acc += sh[w][k] * W[k * NHH + j];
        if (lane < 12) {
            acc += dt_bias[j];
            float sp = (acc > 20.f) ? acc : log1pf(expf(acc));
            gk[row * NHH + j] = -expf(A_log[j]) * sp;
        } else {
            acc += bb[j];
            beta[row * NHH + j] = 1.f / (1.f + expf(-acc));
        }
    }
}

// ================= conv + silu + l2norm (q & k in one launch) =================
__global__ void conv_silu_l2qk(const float* __restrict__ qkvg,
                               const float* __restrict__ wq, const float* __restrict__ wk,
                               float* __restrict__ outq, float* __restrict__ outk) {
    int idx = blockIdx.x;
    int which = idx & 1;
    idx >>= 1;
    int h  = idx % NHH;
    int bl = idx / NHH;
    int l  = bl % LL;
    int c  = h * DKK + threadIdx.x;
    const float* in = qkvg + (which ? 768 : 0);
    const float* wr = (which ? wk : wq) + c * 4;
    float* out = which ? outk : outq;
    float acc = 0.f;
#pragma unroll
    for (int j = 0; j < 4; j++) {
        int tt = l - 3 + j;
        if (tt >= 0) acc += in[(size_t)(bl - l + tt) * NTOT + c] * wr[j];
    }
    float sv = acc / (1.f + expf(-acc));
    float ss = sv * sv;
#pragma unroll
    for (int off = 16; off; off >>= 1) ss += __shfl_xor_sync(0xffffffffu, ss, off);
    __shared__ float sred[2];
    if ((threadIdx.x & 31) == 0) sred[threadIdx.x >> 5] = ss;
    __syncthreads();
    float n = sqrtf(sred[0] + sred[1]);
    out[(size_t)bl * KD + c] = sv / fmaxf(n, 1e-12f);
}

__global__ void conv_silu_v(const float* __restrict__ in, int istride,
                            const float* __restrict__ w, float* __restrict__ out, int total) {
    int gid = blockIdx.x * blockDim.x + threadIdx.x;
    if (gid >= total) return;
    int c  = gid % VD;
    int bl = gid / VD;
    int l  = bl % LL;
    const float* wr = w + c * 4;
    float acc = 0.f;
#pragma unroll
    for (int j = 0; j < 4; j++) {
        int tt = l - 3 + j;
        if (tt >= 0) acc += in[(size_t)(bl - l + tt) * istride + c] * wr[j];
    }
    out[gid] = acc / (1.f + expf(-acc));
}

// ================= recurrence v5: 16-step groups =================
#define TS 16
__global__ void __launch_bounds__(128)
recur5(const float* __restrict__ q, const float* __restrict__ k,
       const float* __restrict__ v, const float* __restrict__ gk,
       const float* __restrict__ beta, float* __restrict__ o) {
    int blk = blockIdx.x;
    int b  = blk / (NHH * 2);
    int h  = (blk >> 1) % NHH;
    int vh = blk & 1;
    int tid = threadIdx.x;
    int col  = tid >> 1;
    int half = tid & 1;

    __shared__ float ksh[2][TS][64];
    __shared__ float qsh[2][TS][64];
    __shared__ float vsh[2][TS][64];
    __shared__ float egsh[LL];
    __shared__ float bsh[LL];

    const float* qb = q + (size_t)b * LL * KD + h * DKK;
    const float* kb = k + (size_t)b * LL * KD + h * DKK;
    const float* vb = v + (size_t)b * LL * VD + h * DVV + vh * 64;
    const float* gb = gk + (size_t)b * LL * NHH + h;
    const float* be = beta + (size_t)b * LL * NHH + h;
    float* ob = o + (size_t)b * LL * VD + h * DVV + vh * 64;

    for (int i = tid; i < LL; i += 128) {
        egsh[i] = expf(gb[(size_t)i * NHH]);
        bsh[i]  = be[(size_t)i * NHH];
    }

    u64 S2[16];
#pragma unroll
    for (int i = 0; i < 16; i++) S2[i] = 0ull;

    const int ls = tid >> 6;   // 0..1
    const int lc = tid & 63;
#pragma unroll
    for (int i = 0; i < TS / 2; i++) {
        int s = i * 2 + ls;
        ksh[0][s][lc] = kb[(size_t)s * KD + lc];
        qsh[0][s][lc] = qb[(size_t)s * KD + lc];
        vsh[0][s][lc] = vb[(size_t)s * VD + lc];
    }
    __syncthreads();

    const int NG = LL / TS;
    for (int g = 0; g < NG; g++) {
        const int buf = g & 1;
        float rk[TS / 2], rq[TS / 2], rv[TS / 2];
        const bool more = (g + 1) < NG;
        if (more) {
            int t0 = (g + 1) * TS;
#pragma unroll
            for (int i = 0; i < TS / 2; i++) {
                int s = i * 2 + ls;
                rk[i] = kb[(size_t)(t0 + s) * KD + lc];
                rq[i] = qb[(size_t)(t0 + s) * KD + lc];
                rv[i] = vb[(size_t)(t0 + s) * VD + lc];
            }
        }
#pragma unroll
        for (int s = 0; s < TS; s++) {
            int t = g * TS + s;
            float eg = egsh[t], bt = bsh[t];
            float vv = vsh[buf][s][col];
            const u64* kh2 = (const u64*)&ksh[buf][s][half * 32];
            const u64* qh2 = (const u64*)&qsh[buf][s][half * 32];

            u64 eg2; DUP2(eg2, __float_as_uint(eg));
            u64 p0 = 0ull, p1 = 0ull, p2 = 0ull, p3 = 0ull;
#pragma unroll
            for (int j = 0; j < 16; j += 4) {
                MUL2(S2[j],     S2[j],     eg2);
                MUL2(S2[j + 1], S2[j + 1], eg2);
                MUL2(S2[j + 2], S2[j + 2], eg2);
                MUL2(S2[j + 3], S2[j + 3], eg2);
                FMA2(p0, kh2[j],     S2[j]);
                FMA2(p1, kh2[j + 1], S2[j + 1]);
                FMA2(p2, kh2[j + 2], S2[j + 2]);
                FMA2(p3, kh2[j + 3], S2[j + 3]);
            }
            u32 a0, a1, a2, a3, a4, a5, a6, a7;
            UNPK2(a0, a1, p0); UNPK2(a2, a3, p1);
            UNPK2(a4, a5, p2); UNPK2(a6, a7, p3);
            float pred = ((__uint_as_float(a0) + __uint_as_float(a1)) +
                          (__uint_as_float(a2) + __uint_as_float(a3))) +
                         ((__uint_as_float(a4) + __uint_as_float(a5)) +
                          (__uint_as_float(a6) + __uint_as_float(a7)));
            pred += __shfl_xor_sync(0xffffffffu, pred, 1);
            float delta = bt * (vv - pred);

            u64 d2; DUP2(d2, __float_as_uint(delta));
            u64 o0 = 0ull, o1 = 0ull, o2 = 0ull, o3 = 0ull;
#pragma unroll
            for (int j = 0; j < 16; j += 4) {
                FMA2(S2[j],     kh2[j],     d2);
                FMA2(S2[j + 1], kh2[j + 1], d2);
                FMA2(S2[j + 2], kh2[j + 2], d2);
                FMA2(S2[j + 3], kh2[j + 3], d2);
                FMA2(o0, qh2[j],     S2[j]);
                FMA2(o1, qh2[j + 1], S2[j + 1]);
                FMA2(o2, qh2[j + 2], S2[j + 2]);
                FMA2(o3, qh2[j + 3], S2[j + 3]);
            }
            UNPK2(a0, a1, o0); UNPK2(a2, a3, o1);
            UNPK2(a4, a5, o2); UNPK2(a6, a7, o3);
            float out = ((__uint_as_float(a0) + __uint_as_float(a1)) +
                         (__uint_as_float(a2) + __uint_as_float(a3))) +
                        ((__uint_as_float(a4) + __uint_as_float(a5)) +
                         (__uint_as_float(a6) + __uint_as_float(a7)));
            out += __shfl_xor_sync(0xffffffffu, out, 1);
            if (half == 0) ob[(size_t)t * VD + col] = out;
        }
        if (more) {
#pragma unroll
            for (int i = 0; i < TS / 2; i++) {
                int s = i * 2 + ls;
                ksh[buf ^ 1][s][lc] = rk[i];
                qsh[buf ^ 1][s][lc] = rq[i];
                vsh[buf ^ 1][s][lc] = rv[i];
            }
        }
        __syncthreads();
    }
}

// ================= rmsnorm * gnorm_w * silu(g) -> hi/lo bf16 =================
__global__ void rmsgate_kernel(const float* __restrict__ o, const float* __restrict__ g,
                               const float* __restrict__ gw,
                               __nv_bfloat16* __restrict__ oh, __nv_bfloat16* __restrict__ ol) {
    int bl = blockIdx.x / NHH, h = blockIdx.x % NHH;
    size_t obase = (size_t)blockIdx.x * DVV;
    size_t gbase = (size_t)bl * NTOT + h * DVV;
    int tid = threadIdx.x;
    float val = o[obase + tid];
    float ss = val * val;
#pragma unroll
    for (int off = 16; off; off >>= 1) ss += __shfl_xor_sync(0xffffffffu, ss, off);
    __shared__ float sr[4];
    if ((tid & 31) == 0) sr[tid >> 5] = ss;
    __syncthreads();
    float tot = sr[0] + sr[1] + sr[2] + sr[3];
    float r = rsqrtf(tot / DVV + 1e-5f);
    float gv = g[gbase + tid];
    float sgt = gv / (1.f + expf(-gv));
    float res = val * r * gw[tid] * sgt;
    __nv_bfloat16 hi = __float2bfloat16(res);
    oh[obase + tid] = hi;
    ol[obase + tid] = __float2bfloat16(res - __bfloat162float(hi));
}

// ================= launch =================
extern "C" void kernel_launch(void* const* d_in, const int* in_sizes, int n_in,
                              void* d_out, int out_size) {
    const float *hs = 0, *Wq = 0, *Wk = 0, *Wv = 0, *Wg = 0, *Wgk = 0, *Wb = 0,
                *bbp = 0, *convq = 0, *convk = 0, *convv = 0, *Alog = 0,
                *dtb = 0, *gnw = 0, *Wo = 0;
    int c786 = 0, c1572 = 0, c12288 = 0, c12 = 0, c3072 = 0;
    for (int i = 0; i < n_in; i++) {
        const float* p = (const float*)d_in[i];
        switch (in_sizes[i]) {
            case 8388608: hs = p; break;
            case 786432:  if (c786++ == 0) Wq = p; else Wk = p; break;
            case 1572864: { int j = c1572++; if (j == 0) Wv = p; else if (j == 1) Wg = p; else Wo = p; } break;
            case 12288:   if (c12288++ == 0) Wgk = p; else Wb = p; break;
            case 12:      { int j = c12++; if (j == 0) bbp = p; else if (j == 1) Alog = p; else dtb = p; } break;
            case 3072:    if (c3072++ == 0) convq = p; else convk = p; break;
            case 6144:    convv = p; break;
            case 128:     gnw = p; break;
            default: break;
        }
    }

    float *qkvg, *bQc, *bKc, *bVc, *bO, *bgk, *bbe;
    __nv_bfloat16 *hsh, *hsl, *wth, *wtl, *woth, *wotl, *oh, *ol;
    cudaGetSymbolAddress((void**)&qkvg, g_qkvg);
    cudaGetSymbolAddress((void**)&hsh,  g_hsh);
    cudaGetSymbolAddress((void**)&hsl,  g_hsl);
    cudaGetSymbolAddress((void**)&wth,  g_wth);
    cudaGetSymbolAddress((void**)&wtl,  g_wtl);
    cudaGetSymbolAddress((void**)&woth, g_woth);
    cudaGetSymbolAddress((void**)&wotl, g_wotl);
    cudaGetSymbolAddress((void**)&oh,   g_oh);
    cudaGetSymbolAddress((void**)&ol,   g_ol);
    cudaGetSymbolAddress((void**)&bQc,  g_bufQc);
    cudaGetSymbolAddress((void**)&bKc,  g_bufKc);
    cudaGetSymbolAddress((void**)&bVc,  g_bufVc);
    cudaGetSymbolAddress((void**)&bO,   g_bufO);
    cudaGetSymbolAddress((void**)&bgk,  g_gk);
    cudaGetSymbolAddress((void**)&bbe,  g_beta);

    cudaFuncSetAttribute(gemm_mma, cudaFuncAttributeMaxDynamicSharedMemorySize, SMEM_GEMM);

    // 1: split, 2: all transposes, 3: gkbeta
    split_kernel<<<(BL * HH + 255) / 256, 256>>>(hs, hsh, hsl, BL * HH);
    transp_all<<<6144, dim3(32, 8)>>>(Wq, Wk, Wv, Wg, Wo, wth, wtl, woth, wotl);
    gkbeta2<<<BL / 8, 256>>>(hs, Wgk, Wb, bbp, Alog, dtb, bgk, bbe);

    // 4 & 5: QK and VG projections (both gemm_mma so either capture offset profiles the GEMM)
    gemm_mma<<<dim3(12, BL / 128), 256, SMEM_GEMM>>>(hsh, hsl, wth, wtl, qkvg, HH, NTOT);
    gemm_mma<<<dim3(24, BL / 128), 256, SMEM_GEMM>>>(hsh, hsl,
        wth + (size_t)1536 * HH, wtl + (size_t)1536 * HH, qkvg + 1536, HH, NTOT);

    // 6-7: convs
    conv_silu_l2qk<<<BL * NHH * 2, 64>>>(qkvg, convq, convk, bQc, bKc);
    int totv = BL * VD;
    conv_silu_v<<<(totv + 255) / 256, 256>>>(qkvg + 1536, NTOT, convv, bVc, totv);

    // 8: recurrence
    recur5<<<BB * NHH * 2, 128>>>(bQc, bKc, bVc, bgk, bbe, bO);

    // 9: rmsnorm + swish gate
    rmsgate_kernel<<<BL * NHH, 128>>>(bO, qkvg + 3072, gnw, oh, ol);

    // 10: output projection
    gemm_mma<<<dim3(HH / 128, BL / 128), 256, SMEM_GEMM>>>(oh, ol, woth, wotl, (float*)d_out, VD, HH);
}